// round 2
// baseline (speedup 1.0000x reference)
#include <cuda_runtime.h>
#include <cstdint>
#include <cstddef>

#define B_ROWS 32768
#define DDIM   128
#define HDIM   64
#define NSTEPS 32
#define TILE_R 64
#define CTA_THREADS 256
#define SROW   68   // padded row stride (floats): even (8B-aligned pairs), 272B rows

// Pre-transposed / gate-packed weight scratch (allowed: __device__ globals)
__device__ float4 g_W0p[192 * 64];   // [k][unit] -> (Wi,Wf,Wg,Wo), k: 0..127 = y-input, 128..191 = h0
__device__ float4 g_W1p[128 * 64];   // [k][unit], k: 0..63 = h0-input, 64..127 = h1
__device__ float  g_WfcT[64 * 128];  // [k][d]

// ---------- packed f32x2 helpers ----------
static __device__ __forceinline__ unsigned long long pack2(float lo, float hi) {
    unsigned long long r;
    asm("mov.b64 %0, {%1, %2};" : "=l"(r) : "f"(lo), "f"(hi));
    return r;
}
static __device__ __forceinline__ void unpack2(unsigned long long v, float& lo, float& hi) {
    asm("mov.b64 {%0, %1}, %2;" : "=f"(lo), "=f"(hi) : "l"(v));
}
static __device__ __forceinline__ unsigned long long ffma2(unsigned long long a,
                                                           unsigned long long b,
                                                           unsigned long long c) {
    unsigned long long d;
    asm("fma.rn.f32x2 %0, %1, %2, %3;" : "=l"(d) : "l"(a), "l"(b), "l"(c));
    return d;
}

static __device__ __forceinline__ float sigm(float x) {
    return __fdividef(1.0f, 1.0f + __expf(-x));
}
static __device__ __forceinline__ float tanh_fast(float x) {
    float e = __expf(-2.0f * fabsf(x));
    float t = __fdividef(1.0f - e, 1.0f + e);
    return copysignf(t, x);
}

// ---------- weight prep: transpose + gate-pack ----------
__global__ void prep_kernel(const float* __restrict__ Wih0, const float* __restrict__ Whh0,
                            const float* __restrict__ Wih1, const float* __restrict__ Whh1,
                            const float* __restrict__ Wfc) {
    int i = blockIdx.x * blockDim.x + threadIdx.x;
    int stride = gridDim.x * blockDim.x;

    for (int idx = i; idx < 192 * 64; idx += stride) {
        int k = idx >> 6, u = idx & 63;
        float4 v;
        if (k < 128) {
            v.x = Wih0[(u      ) * 128 + k];
            v.y = Wih0[(u +  64) * 128 + k];
            v.z = Wih0[(u + 128) * 128 + k];
            v.w = Wih0[(u + 192) * 128 + k];
        } else {
            int kk = k - 128;
            v.x = Whh0[(u      ) * 64 + kk];
            v.y = Whh0[(u +  64) * 64 + kk];
            v.z = Whh0[(u + 128) * 64 + kk];
            v.w = Whh0[(u + 192) * 64 + kk];
        }
        g_W0p[idx] = v;
    }
    for (int idx = i; idx < 128 * 64; idx += stride) {
        int k = idx >> 6, u = idx & 63;
        float4 v;
        if (k < 64) {
            v.x = Wih1[(u      ) * 64 + k];
            v.y = Wih1[(u +  64) * 64 + k];
            v.z = Wih1[(u + 128) * 64 + k];
            v.w = Wih1[(u + 192) * 64 + k];
        } else {
            int kk = k - 64;
            v.x = Whh1[(u      ) * 64 + kk];
            v.y = Whh1[(u +  64) * 64 + kk];
            v.z = Whh1[(u + 128) * 64 + kk];
            v.w = Whh1[(u + 192) * 64 + kk];
        }
        g_W1p[idx] = v;
    }
    for (int idx = i; idx < 64 * 128; idx += stride) {
        int k = idx >> 7, d = idx & 127;
        g_WfcT[idx] = Wfc[d * 64 + k];
    }
}

// Accumulate 4 gates over nK features from state array s_base (k-major, stride SROW),
// weights from Wp starting at k-row kw0. Rows are the 8 f32x2 pairs at r0.
static __device__ __forceinline__ void gate_accum(
    const float4* __restrict__ Wp, int kw0, int nK, int u,
    const float* __restrict__ s_base, int r0,
    unsigned long long* ai, unsigned long long* af,
    unsigned long long* ag, unsigned long long* ao) {
#pragma unroll 4
    for (int k = 0; k < nK; ++k) {
        float4 wv = Wp[(kw0 + k) * 64 + u];
        unsigned long long wi = pack2(wv.x, wv.x);
        unsigned long long wf = pack2(wv.y, wv.y);
        unsigned long long wg = pack2(wv.z, wv.z);
        unsigned long long wo = pack2(wv.w, wv.w);
        const unsigned long long* s =
            reinterpret_cast<const unsigned long long*>(s_base + k * SROW + r0);
#pragma unroll
        for (int p = 0; p < 8; ++p) {
            unsigned long long sv = s[p];
            ai[p] = ffma2(wi, sv, ai[p]);
            af[p] = ffma2(wf, sv, af[p]);
            ag[p] = ffma2(wg, sv, ag[p]);
            ao[p] = ffma2(wo, sv, ao[p]);
        }
    }
}

extern __shared__ float smem[];

__global__ __launch_bounds__(CTA_THREADS, 1)
void lstm_kernel(const float* __restrict__ x,
                 const float* __restrict__ b0, const float* __restrict__ b1,
                 const float* __restrict__ bfc,
                 float* __restrict__ ystack, float* __restrict__ ylast) {
    float* y_sm  = smem;                      // [128][SROW]
    float* h0_sm = y_sm  + DDIM * SROW;       // [64][SROW]
    float* h1_sm = h0_sm + HDIM * SROW;       // [64][SROW]

    const int tid  = threadIdx.x;
    const int lane = tid & 31;
    const int w    = tid >> 5;
    const int row0 = blockIdx.x * TILE_R;

    // Load x tile into y_sm (k-major), zero h states
    for (int i = tid; i < TILE_R * DDIM; i += CTA_THREADS) {
        int r = i >> 7, d = i & 127;
        y_sm[d * SROW + r] = x[(size_t)(row0 + r) * DDIM + d];
    }
    for (int i = tid; i < HDIM * SROW; i += CTA_THREADS) {
        h0_sm[i] = 0.0f;
        h1_sm[i] = 0.0f;
    }

    // LSTM gate role: lane -> unit, rows register-blocked 16/warp
    const int ublk   = w & 1;
    const int rowblk = w >> 1;          // 0..3
    const int u      = ublk * 32 + lane;
    const int r0     = rowblk * 16;

    // FC role: lane -> output dim, 32 rows/warp
    const int dblk    = w & 3;
    const int rowblkF = w >> 2;         // 0..1
    const int d_fc    = dblk * 32 + lane;
    const int rF0     = rowblkF * 32;

    float c0[16], c1[16];
#pragma unroll
    for (int i = 0; i < 16; ++i) { c0[i] = 0.0f; c1[i] = 0.0f; }

    const float bi0 = b0[u], bf0 = b0[64 + u], bg0 = b0[128 + u], bo0 = b0[192 + u];
    const float bi1 = b1[u], bf1 = b1[64 + u], bg1 = b1[128 + u], bo1 = b1[192 + u];
    const float bfc_r = bfc[d_fc];

    for (int t = 0; t < NSTEPS; ++t) {
        __syncthreads();  // states (y, h0, h1) ready

        // ---------------- layer 0 gates ----------------
        unsigned long long ai[8], af[8], ag[8], ao[8];
#pragma unroll
        for (int p = 0; p < 8; ++p) {
            ai[p] = pack2(bi0, bi0); af[p] = pack2(bf0, bf0);
            ag[p] = pack2(bg0, bg0); ao[p] = pack2(bo0, bo0);
        }
        gate_accum(g_W0p,   0, DDIM, u, y_sm,  r0, ai, af, ag, ao);
        gate_accum(g_W0p, 128, HDIM, u, h0_sm, r0, ai, af, ag, ao);

        __syncthreads();  // everyone done reading old h0

#pragma unroll
        for (int p = 0; p < 8; ++p) {
            float iv0, iv1, fv0, fv1, gv0, gv1, ov0, ov1;
            unpack2(ai[p], iv0, iv1);
            unpack2(af[p], fv0, fv1);
            unpack2(ag[p], gv0, gv1);
            unpack2(ao[p], ov0, ov1);
            float c;
            c = sigm(fv0) * c0[2 * p]     + sigm(iv0) * tanh_fast(gv0);
            c0[2 * p] = c;
            h0_sm[u * SROW + r0 + 2 * p]     = sigm(ov0) * tanh_fast(c);
            c = sigm(fv1) * c0[2 * p + 1] + sigm(iv1) * tanh_fast(gv1);
            c0[2 * p + 1] = c;
            h0_sm[u * SROW + r0 + 2 * p + 1] = sigm(ov1) * tanh_fast(c);
        }

        __syncthreads();  // new h0 visible

        // ---------------- layer 1 gates ----------------
#pragma unroll
        for (int p = 0; p < 8; ++p) {
            ai[p] = pack2(bi1, bi1); af[p] = pack2(bf1, bf1);
            ag[p] = pack2(bg1, bg1); ao[p] = pack2(bo1, bo1);
        }
        gate_accum(g_W1p,  0, HDIM, u, h0_sm, r0, ai, af, ag, ao);
        gate_accum(g_W1p, 64, HDIM, u, h1_sm, r0, ai, af, ag, ao);

        __syncthreads();  // everyone done reading old h1

#pragma unroll
        for (int p = 0; p < 8; ++p) {
            float iv0, iv1, fv0, fv1, gv0, gv1, ov0, ov1;
            unpack2(ai[p], iv0, iv1);
            unpack2(af[p], fv0, fv1);
            unpack2(ag[p], gv0, gv1);
            unpack2(ao[p], ov0, ov1);
            float c;
            c = sigm(fv0) * c1[2 * p]     + sigm(iv0) * tanh_fast(gv0);
            c1[2 * p] = c;
            h1_sm[u * SROW + r0 + 2 * p]     = sigm(ov0) * tanh_fast(c);
            c = sigm(fv1) * c1[2 * p + 1] + sigm(iv1) * tanh_fast(gv1);
            c1[2 * p + 1] = c;
            h1_sm[u * SROW + r0 + 2 * p + 1] = sigm(ov1) * tanh_fast(c);
        }

        __syncthreads();  // new h1 visible

        // ---------------- FC projection: y = Wfc @ h1 + bfc ----------------
        unsigned long long ay[16];
#pragma unroll
        for (int p = 0; p < 16; ++p) ay[p] = pack2(bfc_r, bfc_r);
#pragma unroll 4
        for (int k = 0; k < HDIM; ++k) {
            float wv = g_WfcT[k * 128 + d_fc];
            unsigned long long wp = pack2(wv, wv);
            const unsigned long long* s =
                reinterpret_cast<const unsigned long long*>(h1_sm + k * SROW + rF0);
#pragma unroll
            for (int p = 0; p < 16; ++p) ay[p] = ffma2(wp, s[p], ay[p]);
        }

        const size_t tbase = (size_t)t * B_ROWS * DDIM;
#pragma unroll
        for (int p = 0; p < 16; ++p) {
            float ylo, yhi;
            unpack2(ay[p], ylo, yhi);
            const int r = rF0 + 2 * p;
            y_sm[d_fc * SROW + r]     = ylo;
            y_sm[d_fc * SROW + r + 1] = yhi;
            if (ystack) {
                ystack[tbase + (size_t)(row0 + r)     * DDIM + d_fc] = ylo;
                ystack[tbase + (size_t)(row0 + r + 1) * DDIM + d_fc] = yhi;
            }
            if (t == NSTEPS - 1 && ylast) {
                ylast[(size_t)(row0 + r)     * DDIM + d_fc] = ylo;
                ylast[(size_t)(row0 + r + 1) * DDIM + d_fc] = yhi;
            }
        }
        // next-iteration top sync guards y_sm reads
    }
}

extern "C" void kernel_launch(void* const* d_in, const int* in_sizes, int n_in,
                              void* d_out, int out_size) {
    const float* x    = (const float*)d_in[0];
    const float* Wih0 = (const float*)d_in[1];
    const float* Whh0 = (const float*)d_in[2];
    const float* b0   = (const float*)d_in[3];
    const float* Wih1 = (const float*)d_in[4];
    const float* Whh1 = (const float*)d_in[5];
    const float* b1   = (const float*)d_in[6];
    const float* Wfc  = (const float*)d_in[7];
    const float* bfc  = (const float*)d_in[8];
    (void)in_sizes; (void)n_in;

    float* out = (float*)d_out;
    const long long BD = (long long)B_ROWS * DDIM;

    float* ylast  = nullptr;
    float* ystack = nullptr;
    if ((long long)out_size >= BD * (NSTEPS + 1)) {        // [y_last, y_stack]
        ylast  = out;
        ystack = out + BD;
    } else if ((long long)out_size >= BD * NSTEPS) {       // y_stack only
        ystack = out;
    } else {                                               // y_last only
        ylast = out;
    }

    const int smem_bytes = (DDIM + HDIM + HDIM) * SROW * sizeof(float);  // 69632
    cudaFuncSetAttribute(lstm_kernel, cudaFuncAttributeMaxDynamicSharedMemorySize, smem_bytes);

    prep_kernel<<<64, 256>>>(Wih0, Whh0, Wih1, Whh1, Wfc);
    lstm_kernel<<<B_ROWS / TILE_R, CTA_THREADS, smem_bytes>>>(x, b0, b1, bfc, ystack, ylast);
}

// round 7
// speedup vs baseline: 1.8062x; 1.8062x over previous
#include <cuda_runtime.h>
#include <cuda_bf16.h>
#include <cstdint>
#include <cstddef>

#define B_ROWS 32768
#define DDIM   128
#define NSTEPS 32
#define THREADS 256
#define NONE_OFF 0xFFFFFFFFu

// ---------------- packed weight scratch: one big array ----------------
// [W0h 49152][W0l 49152][W1h 32768][W1l 32768][Wfh 8192][Wfl 8192] bf16 elems
// Each 16384-elem chunk = [256 n x 64 k], 128B rows, SW128 swizzled.
// Gate chunks use unit-interleaved n: n = (u>>3)*32 + g*8 + (u&7).
__device__ __align__(128) __nv_bfloat16 g_WB[180224];

#define SWZ128(o) ((o) ^ (((o) >> 3) & 0x70))

static __device__ __forceinline__ uint32_t smem_u32(const void* p) {
    uint32_t a;
    asm("{ .reg .u64 t; cvta.to.shared.u64 t, %1; cvt.u32.u64 %0, t; }" : "=r"(a) : "l"(p));
    return a;
}

// ---------------- mma / ldmatrix / cp.async ----------------
static __device__ __forceinline__ void ldm_x4(uint32_t* r, uint32_t addr) {
    asm volatile("ldmatrix.sync.aligned.m8n8.x4.shared.b16 {%0,%1,%2,%3}, [%4];"
                 : "=r"(r[0]), "=r"(r[1]), "=r"(r[2]), "=r"(r[3]) : "r"(addr));
}
static __device__ __forceinline__ void mma16816(float* c, const uint32_t* a, const uint32_t* b) {
    asm volatile(
        "mma.sync.aligned.m16n8k16.row.col.f32.bf16.bf16.f32 "
        "{%0,%1,%2,%3}, {%4,%5,%6,%7}, {%8,%9}, {%0,%1,%2,%3};"
        : "+f"(c[0]), "+f"(c[1]), "+f"(c[2]), "+f"(c[3])
        : "r"(a[0]), "r"(a[1]), "r"(a[2]), "r"(a[3]), "r"(b[0]), "r"(b[1]));
}
static __device__ __forceinline__ void cp16(uint32_t dst, const void* src) {
    asm volatile("cp.async.cg.shared.global [%0], [%1], 16;" :: "r"(dst), "l"(src));
}
static __device__ __forceinline__ void cp_commit() {
    asm volatile("cp.async.commit_group;" ::: "memory");
}

static __device__ __forceinline__ float sigm(float x) {
    return __fdividef(1.0f, 1.0f + __expf(-x));
}
static __device__ __forceinline__ float tanh_fast(float x) {
    float e = __expf(-2.0f * fabsf(x));
    float t = __fdividef(1.0f - e, 1.0f + e);
    return copysignf(t, x);
}

// ---------------- smem layout (byte offsets in dynamic smem) ----------------
#define T_YH0 0
#define T_YH1 16384
#define T_YL0 32768
#define T_YL1 49152
#define T_H0H 65536
#define T_H0L 81920
#define T_H1H 98304
#define T_H1L 114688
#define SM_WBUF 131072              /* 2 x 32KB stream buffers */
#define SM_TOTAL 196608

// ---------------- per-step chunk sequence (12 per M-pass, 24 total) ----------------
__constant__ uint32_t c_src[12] = {
    0, 16384, 32768,          // L0 hi: k-blocks y0,y1,h0
    49152, 65536, 81920,      // L0 lo
    98304, 114688,            // L1 hi: h0,h1
    131072, 147456,           // L1 lo
    163840, 172032            // FC hi, lo
};
__constant__ uint32_t c_bytes[12] = {
    32768, 32768, 32768, 32768, 32768, 32768,
    32768, 32768, 32768, 32768, 16384, 16384
};
__constant__ uint32_t c_ahi[12] = {
    T_YH0, T_YH1, T_H0H, T_YH0, T_YH1, T_H0H,
    T_H0H, T_H1H, T_H0H, T_H1H, T_H1H, T_H1H
};
__constant__ uint32_t c_alo[12] = {
    T_YL0, T_YL1, T_H0L, NONE_OFF, NONE_OFF, NONE_OFF,
    T_H0L, T_H1L, NONE_OFF, NONE_OFF, T_H1L, NONE_OFF
};

// ---------------- weight prep: split + pack + swizzle ----------------
static __device__ __forceinline__ void wpack(uint32_t hi_off, uint32_t lo_off,
                                             int n, int kk, float w) {
    uint32_t sw = SWZ128((uint32_t)n * 128u + (uint32_t)kk * 2u) >> 1;
    __nv_bfloat16 h = __float2bfloat16(w);
    g_WB[hi_off + sw] = h;
    g_WB[lo_off + sw] = __float2bfloat16(w - __bfloat162float(h));
}

__global__ void prep_kernel(const float* __restrict__ Wih0, const float* __restrict__ Whh0,
                            const float* __restrict__ Wih1, const float* __restrict__ Whh1,
                            const float* __restrict__ Wfc) {
    int i = blockIdx.x * blockDim.x + threadIdx.x;
    int stride = gridDim.x * blockDim.x;
    // L0: chunks 0,1 = Wih0 k-blocks; chunk 2 = Whh0. Gate-interleaved n.
    for (int idx = i; idx < 3 * 16384; idx += stride) {
        int ch = idx >> 14, e = idx & 16383, n = e >> 6, kk = e & 63;
        int g = (n >> 3) & 3, u = ((n >> 5) << 3) | (n & 7);
        float w = (ch < 2) ? Wih0[(g * 64 + u) * 128 + ch * 64 + kk]
                           : Whh0[(g * 64 + u) * 64 + kk];
        wpack(0 + ch * 16384, 49152 + ch * 16384, n, kk, w);
    }
    // L1: chunk 0 = Wih1 (h0 input), chunk 1 = Whh1 (h1 state)
    for (int idx = i; idx < 2 * 16384; idx += stride) {
        int ch = idx >> 14, e = idx & 16383, n = e >> 6, kk = e & 63;
        int g = (n >> 3) & 3, u = ((n >> 5) << 3) | (n & 7);
        float w = (ch == 0) ? Wih1[(g * 64 + u) * 64 + kk]
                            : Whh1[(g * 64 + u) * 64 + kk];
        wpack(98304 + ch * 16384, 131072 + ch * 16384, n, kk, w);
    }
    // FC: plain n = d ordering, [128 x 64]
    for (int idx = i; idx < 8192; idx += stride) {
        int n = idx >> 6, kk = idx & 63;
        wpack(163840, 172032, n, kk, Wfc[n * 64 + kk]);
    }
}

// ---------------- activation hi/lo store ----------------
static __device__ __forceinline__ void st_hilo2(char* th, char* tl, uint32_t off,
                                                float a, float b) {
    uint32_t sw = SWZ128(off);
    __nv_bfloat16 ah = __float2bfloat16(a), bh = __float2bfloat16(b);
    __nv_bfloat162 hp; hp.x = ah; hp.y = bh;
    *(__nv_bfloat162*)(th + sw) = hp;
    __nv_bfloat162 lp;
    lp.x = __float2bfloat16(a - __bfloat162float(ah));
    lp.y = __float2bfloat16(b - __bfloat162float(bh));
    *(__nv_bfloat162*)(tl + sw) = lp;
}

// ---------------- main kernel ----------------
extern __shared__ char smem[];

__global__ __launch_bounds__(THREADS, 1)
void lstm_hmma_kernel(const float* __restrict__ x,
                      const float* __restrict__ b0, const float* __restrict__ b1,
                      const float* __restrict__ bfc,
                      float* __restrict__ ystack, float* __restrict__ ylast) {
    const uint32_t sbase = smem_u32(smem);
    const int tid = threadIdx.x, lane = tid & 31, w = tid >> 5;
    const int row0 = blockIdx.x * 128;

    // ---- init: x -> Y tiles, zero H tiles ----
    {
        uint4 z = make_uint4(0, 0, 0, 0);
        for (uint32_t i = (uint32_t)tid * 16u; i < 65536u; i += 4096u)
            *(uint4*)(smem + T_H0H + i) = z;
        const float4* x4 = (const float4*)(x + (size_t)row0 * 128);
        for (int e = tid; e < 128 * 32; e += THREADS) {
            int r = e >> 5, c4 = e & 31;
            float4 v = x4[r * 32 + c4];
            int c = c4 * 4;
            char* th = (char*)smem + ((c < 64) ? T_YH0 : T_YH1);
            char* tl = (char*)smem + ((c < 64) ? T_YL0 : T_YL1);
            uint32_t off = (uint32_t)r * 128u + (uint32_t)(c & 63) * 2u;
            st_hilo2(th, tl, off, v.x, v.y);
            st_hilo2(th, tl, off + 4, v.z, v.w);
        }
    }

    // ---- per-thread roles ----
    const int l4 = lane >> 2;           // row within 8
    const int ln = lane & 3;            // n-pair selector
    const int u0 = w * 8 + 2 * ln;      // this thread's unit pair (gates)

    // bias preload (acc-init values)
    float b0r[4][2], b1r[4][2], bfr[2][2];
#pragma unroll
    for (int v = 0; v < 4; ++v)
#pragma unroll
        for (int j = 0; j < 2; ++j) {
            b0r[v][j] = b0[v * 64 + u0 + j];
            b1r[v][j] = b1[v * 64 + u0 + j];
        }
#pragma unroll
    for (int v = 0; v < 2; ++v)
#pragma unroll
        for (int j = 0; j < 2; ++j)
            bfr[v][j] = bfc[w * 16 + v * 8 + 2 * ln + j];

    float c0s[32], c1s[32];
#pragma unroll
    for (int i = 0; i < 32; ++i) { c0s[i] = 0.0f; c1s[i] = 0.0f; }

    float acc[4][4][4];

    const __nv_bfloat16* wb = g_WB;

    // prologue: issue chunk 0
    {
        const char* src = (const char*)(wb + c_src[0]);
        uint32_t dst = sbase + SM_WBUF;
        for (uint32_t off = (uint32_t)tid * 16u; off < c_bytes[0]; off += 4096u)
            cp16(dst + off, src + off);
        cp_commit();
    }

#pragma unroll 1
    for (int t = 0; t < NSTEPS; ++t) {
#pragma unroll 1
        for (int c = 0; c < 24; ++c) {
            const int cc = c % 12;
            const int mp = c >= 12;
            const bool isFC = (cc >= 10);
            const int epi = (cc == 5) ? 1 : (cc == 9) ? 2 : (cc == 11) ? 3 : 0;
            const bool start = (cc == 0) | (cc == 6) | (cc == 10);

            __syncthreads();   // protects buffer (c+1)&1 + orders activation tile writes

            // issue next chunk (wrap to next step's chunk 0)
            const bool last = (t == NSTEPS - 1) && (c == 23);
            if (!last) {
                int nc = (c + 1) % 24, ncc = nc % 12;
                const char* src = (const char*)(wb + c_src[ncc]);
                uint32_t dst = sbase + SM_WBUF + (uint32_t)(nc & 1) * 32768u;
                uint32_t nbytes = c_bytes[ncc];
                for (uint32_t off = (uint32_t)tid * 16u; off < nbytes; off += 4096u)
                    cp16(dst + off, src + off);
                cp_commit();
                asm volatile("cp.async.wait_group 1;" ::: "memory");
            } else {
                asm volatile("cp.async.wait_group 0;" ::: "memory");
            }
            __syncthreads();   // chunk c visible to all

            // ---- acc init at phase start ----
            if (start) {
                if (isFC) {
#pragma unroll
                    for (int s = 0; s < 4; ++s)
#pragma unroll
                        for (int v = 0; v < 4; ++v)
#pragma unroll
                            for (int q = 0; q < 4; ++q)
                                acc[s][v][q] = (v < 2) ? bfr[v][q & 1] : 0.0f;
                } else {
                    const bool l0 = (cc == 0);
#pragma unroll
                    for (int s = 0; s < 4; ++s)
#pragma unroll
                        for (int v = 0; v < 4; ++v)
#pragma unroll
                            for (int q = 0; q < 4; ++q)
                                acc[s][v][q] = l0 ? b0r[v][q & 1] : b1r[v][q & 1];
                }
            }

            // ---- mma over this chunk (64 k) ----
            const uint32_t buf = sbase + SM_WBUF + (uint32_t)(c & 1) * 32768u;
            const uint32_t ahi = sbase + c_ahi[cc];
            const uint32_t alo_off = c_alo[cc];
            const bool haslo = (alo_off != NONE_OFF);
            const uint32_t alo = sbase + alo_off;
            const int nbase = isFC ? (w * 16) : (w * 32);
            const int arow_b = mp * 64 + (lane & 15);

#pragma unroll
            for (int k16 = 0; k16 < 4; ++k16) {
                const uint32_t colb = (uint32_t)(k16 * 32 + ((lane >> 4) << 4));
                // B fragments
                uint32_t bf[4][2];
                {
                    uint32_t r[4];
                    uint32_t bo = (uint32_t)(nbase + (lane & 15)) * 128u + colb;
                    ldm_x4(r, buf + SWZ128(bo));
                    bf[0][0] = r[0]; bf[1][0] = r[1]; bf[0][1] = r[2]; bf[1][1] = r[3];
                    if (!isFC) {
                        uint32_t bo2 = (uint32_t)(nbase + 16 + (lane & 15)) * 128u + colb;
                        ldm_x4(r, buf + SWZ128(bo2));
                        bf[2][0] = r[0]; bf[3][0] = r[1]; bf[2][1] = r[2]; bf[3][1] = r[3];
                    }
                }
                const int nt = isFC ? 2 : 4;
#pragma unroll
                for (int s = 0; s < 4; ++s) {
                    uint32_t ao = (uint32_t)(arow_b + s * 16) * 128u + colb;
                    uint32_t ah[4];
                    ldm_x4(ah, ahi + SWZ128(ao));
                    if (haslo) {
                        uint32_t al[4];
                        ldm_x4(al, alo + SWZ128(ao));
#pragma unroll
                        for (int v = 0; v < 4; ++v) {
                            if (v >= nt) break;
                            mma16816(acc[s][v], ah, bf[v]);
                            mma16816(acc[s][v], al, bf[v]);
                        }
                    } else {
#pragma unroll
                        for (int v = 0; v < 4; ++v) {
                            if (v >= nt) break;
                            mma16816(acc[s][v], ah, bf[v]);
                        }
                    }
                }
            }

            // ---- epilogues ----
            if (epi == 1 || epi == 2) {
                __syncthreads();   // all mma reads of H tile done before overwrite
                float* cst = (epi == 1) ? c0s : c1s;
                char* th = (char*)smem + ((epi == 1) ? T_H0H : T_H1H);
                char* tl = (char*)smem + ((epi == 1) ? T_H0L : T_H1L);
#pragma unroll
                for (int s = 0; s < 4; ++s)
#pragma unroll
                    for (int rh = 0; rh < 2; ++rh) {
                        float h2[2];
#pragma unroll
                        for (int j = 0; j < 2; ++j) {
                            float iv = sigm(acc[s][0][rh * 2 + j]);
                            float fv = sigm(acc[s][1][rh * 2 + j]);
                            float gv = tanh_fast(acc[s][2][rh * 2 + j]);
                            float ov = sigm(acc[s][3][rh * 2 + j]);
                            int ci = mp * 16 + s * 4 + rh * 2 + j;
                            float cv = fv * cst[ci] + iv * gv;
                            cst[ci] = cv;
                            h2[j] = ov * tanh_fast(cv);
                        }
                        int row = mp * 64 + s * 16 + l4 + rh * 8;
                        st_hilo2(th, tl, (uint32_t)row * 128u + (uint32_t)u0 * 2u,
                                 h2[0], h2[1]);
                    }
            } else if (epi == 3) {
                // FC epilogue: y = acc (+bias already), write gmem + Y tiles
                const size_t tb = (size_t)t * B_ROWS * DDIM;
#pragma unroll
                for (int s = 0; s < 4; ++s)
#pragma unroll
                    for (int rh = 0; rh < 2; ++rh) {
                        int row = mp * 64 + s * 16 + l4 + rh * 8;
                        float* ys = ystack ? (ystack + tb + (size_t)(row0 + row) * DDIM)
                                           : nullptr;
                        float* yl = (ylast && t == NSTEPS - 1)
                                        ? (ylast + (size_t)(row0 + row) * DDIM) : nullptr;
#pragma unroll
                        for (int v = 0; v < 2; ++v) {
                            int d = w * 16 + v * 8 + 2 * ln;
                            float y0 = acc[s][v][rh * 2 + 0];
                            float y1 = acc[s][v][rh * 2 + 1];
                            if (ys) { float2 p = make_float2(y0, y1); *(float2*)(ys + d) = p; }
                            if (yl) { float2 p = make_float2(y0, y1); *(float2*)(yl + d) = p; }
                            char* th = (char*)smem + ((d < 64) ? T_YH0 : T_YH1);
                            char* tl = (char*)smem + ((d < 64) ? T_YL0 : T_YL1);
                            st_hilo2(th, tl, (uint32_t)row * 128u + (uint32_t)(d & 63) * 2u,
                                     y0, y1);
                        }
                    }
            }
        }
    }
}

extern "C" void kernel_launch(void* const* d_in, const int* in_sizes, int n_in,
                              void* d_out, int out_size) {
    const float* x    = (const float*)d_in[0];
    const float* Wih0 = (const float*)d_in[1];
    const float* Whh0 = (const float*)d_in[2];
    const float* b0   = (const float*)d_in[3];
    const float* Wih1 = (const float*)d_in[4];
    const float* Whh1 = (const float*)d_in[5];
    const float* b1   = (const float*)d_in[6];
    const float* Wfc  = (const float*)d_in[7];
    const float* bfc  = (const float*)d_in[8];
    (void)in_sizes; (void)n_in;

    float* out = (float*)d_out;
    const long long BD = (long long)B_ROWS * DDIM;
    float* ylast  = nullptr;
    float* ystack = nullptr;
    if ((long long)out_size >= BD * (NSTEPS + 1)) {
        ylast  = out;
        ystack = out + BD;
    } else if ((long long)out_size >= BD * NSTEPS) {
        ystack = out;
    } else {
        ylast = out;
    }

    cudaFuncSetAttribute(lstm_hmma_kernel,
                         cudaFuncAttributeMaxDynamicSharedMemorySize, SM_TOTAL);

    prep_kernel<<<64, 256>>>(Wih0, Whh0, Wih1, Whh1, Wfc);
    lstm_hmma_kernel<<<B_ROWS / 128, THREADS, SM_TOTAL>>>(x, b0, b1, bfc, ystack, ylast);
}

// round 8
// speedup vs baseline: 1.8064x; 1.0001x over previous
#include <cuda_runtime.h>
#include <cuda_bf16.h>
#include <cstdint>
#include <cstddef>

#define B_ROWS 32768
#define DDIM   128
#define NSTEPS 32
#define THREADS 256
#define NONE_OFF 0xFFFFFFFFu

// ---------------- packed weight scratch: one big array ----------------
// [W0h 49152][W0l 49152][W1h 32768][W1l 32768][Wfh 8192][Wfl 8192] bf16 elems
// Each 16384-elem chunk = [256 n x 64 k], 128B rows, SW128 swizzled.
// Gate chunks use unit-interleaved n: n = (u>>3)*32 + g*8 + (u&7).
__device__ __align__(128) __nv_bfloat16 g_WB[180224];

#define SWZ128(o) ((o) ^ (((o) >> 3) & 0x70))

static __device__ __forceinline__ uint32_t smem_u32(const void* p) {
    uint32_t a;
    asm("{ .reg .u64 t; cvta.to.shared.u64 t, %1; cvt.u32.u64 %0, t; }" : "=r"(a) : "l"(p));
    return a;
}

// ---------------- mma / ldmatrix / cp.async ----------------
static __device__ __forceinline__ void ldm_x4(uint32_t* r, uint32_t addr) {
    asm volatile("ldmatrix.sync.aligned.m8n8.x4.shared.b16 {%0,%1,%2,%3}, [%4];"
                 : "=r"(r[0]), "=r"(r[1]), "=r"(r[2]), "=r"(r[3]) : "r"(addr));
}
static __device__ __forceinline__ void mma16816(float* c, const uint32_t* a, const uint32_t* b) {
    asm volatile(
        "mma.sync.aligned.m16n8k16.row.col.f32.bf16.bf16.f32 "
        "{%0,%1,%2,%3}, {%4,%5,%6,%7}, {%8,%9}, {%0,%1,%2,%3};"
        : "+f"(c[0]), "+f"(c[1]), "+f"(c[2]), "+f"(c[3])
        : "r"(a[0]), "r"(a[1]), "r"(a[2]), "r"(a[3]), "r"(b[0]), "r"(b[1]));
}
static __device__ __forceinline__ void cp16(uint32_t dst, const void* src) {
    asm volatile("cp.async.cg.shared.global [%0], [%1], 16;" :: "r"(dst), "l"(src));
}
static __device__ __forceinline__ void cp_commit() {
    asm volatile("cp.async.commit_group;" ::: "memory");
}

static __device__ __forceinline__ float sigm(float x) {
    return __fdividef(1.0f, 1.0f + __expf(-x));
}
static __device__ __forceinline__ float tanh_fast(float x) {
    float e = __expf(-2.0f * fabsf(x));
    float t = __fdividef(1.0f - e, 1.0f + e);
    return copysignf(t, x);
}

// ---------------- smem layout (byte offsets in dynamic smem) ----------------
#define T_YH0 0
#define T_YH1 16384
#define T_YL0 32768
#define T_YL1 49152
#define T_H0H 65536
#define T_H0L 81920
#define T_H1H 98304
#define T_H1L 114688
#define SM_WBUF 131072              /* 2 x 32KB stream buffers */
#define SM_TOTAL 196608

// ---------------- per-step chunk sequence (12 per M-pass, 24 total) ----------------
__constant__ uint32_t c_src[12] = {
    0, 16384, 32768,          // L0 hi: k-blocks y0,y1,h0
    49152, 65536, 81920,      // L0 lo
    98304, 114688,            // L1 hi: h0,h1
    131072, 147456,           // L1 lo
    163840, 172032            // FC hi, lo
};
__constant__ uint32_t c_bytes[12] = {
    32768, 32768, 32768, 32768, 32768, 32768,
    32768, 32768, 32768, 32768, 16384, 16384
};
__constant__ uint32_t c_ahi[12] = {
    T_YH0, T_YH1, T_H0H, T_YH0, T_YH1, T_H0H,
    T_H0H, T_H1H, T_H0H, T_H1H, T_H1H, T_H1H
};
__constant__ uint32_t c_alo[12] = {
    T_YL0, T_YL1, T_H0L, NONE_OFF, NONE_OFF, NONE_OFF,
    T_H0L, T_H1L, NONE_OFF, NONE_OFF, T_H1L, NONE_OFF
};

// ---------------- weight prep: split + pack + swizzle ----------------
static __device__ __forceinline__ void wpack(uint32_t hi_off, uint32_t lo_off,
                                             int n, int kk, float w) {
    uint32_t sw = SWZ128((uint32_t)n * 128u + (uint32_t)kk * 2u) >> 1;
    __nv_bfloat16 h = __float2bfloat16(w);
    g_WB[hi_off + sw] = h;
    g_WB[lo_off + sw] = __float2bfloat16(w - __bfloat162float(h));
}

__global__ void prep_kernel(const float* __restrict__ Wih0, const float* __restrict__ Whh0,
                            const float* __restrict__ Wih1, const float* __restrict__ Whh1,
                            const float* __restrict__ Wfc) {
    int i = blockIdx.x * blockDim.x + threadIdx.x;
    int stride = gridDim.x * blockDim.x;
    // L0: chunks 0,1 = Wih0 k-blocks; chunk 2 = Whh0. Gate-interleaved n.
    for (int idx = i; idx < 3 * 16384; idx += stride) {
        int ch = idx >> 14, e = idx & 16383, n = e >> 6, kk = e & 63;
        int g = (n >> 3) & 3, u = ((n >> 5) << 3) | (n & 7);
        float w = (ch < 2) ? Wih0[(g * 64 + u) * 128 + ch * 64 + kk]
                           : Whh0[(g * 64 + u) * 64 + kk];
        wpack(0 + ch * 16384, 49152 + ch * 16384, n, kk, w);
    }
    // L1: chunk 0 = Wih1 (h0 input), chunk 1 = Whh1 (h1 state)
    for (int idx = i; idx < 2 * 16384; idx += stride) {
        int ch = idx >> 14, e = idx & 16383, n = e >> 6, kk = e & 63;
        int g = (n >> 3) & 3, u = ((n >> 5) << 3) | (n & 7);
        float w = (ch == 0) ? Wih1[(g * 64 + u) * 64 + kk]
                            : Whh1[(g * 64 + u) * 64 + kk];
        wpack(98304 + ch * 16384, 131072 + ch * 16384, n, kk, w);
    }
    // FC: plain n = d ordering, [128 x 64]
    for (int idx = i; idx < 8192; idx += stride) {
        int n = idx >> 6, kk = idx & 63;
        wpack(163840, 172032, n, kk, Wfc[n * 64 + kk]);
    }
}

// ---------------- activation hi/lo store ----------------
static __device__ __forceinline__ void st_hilo2(char* th, char* tl, uint32_t off,
                                                float a, float b) {
    uint32_t sw = SWZ128(off);
    __nv_bfloat16 ah = __float2bfloat16(a), bh = __float2bfloat16(b);
    __nv_bfloat162 hp; hp.x = ah; hp.y = bh;
    *(__nv_bfloat162*)(th + sw) = hp;
    __nv_bfloat162 lp;
    lp.x = __float2bfloat16(a - __bfloat162float(ah));
    lp.y = __float2bfloat16(b - __bfloat162float(bh));
    *(__nv_bfloat162*)(tl + sw) = lp;
}

// ---------------- main kernel ----------------
extern __shared__ char smem[];

__global__ __launch_bounds__(THREADS, 1)
void lstm_hmma_kernel(const float* __restrict__ x,
                      const float* __restrict__ b0, const float* __restrict__ b1,
                      const float* __restrict__ bfc,
                      float* __restrict__ ystack, float* __restrict__ ylast) {
    const uint32_t sbase = smem_u32(smem);
    const int tid = threadIdx.x, lane = tid & 31, w = tid >> 5;
    const int row0 = blockIdx.x * 128;

    // ---- init: x -> Y tiles, zero H tiles ----
    {
        uint4 z = make_uint4(0, 0, 0, 0);
        for (uint32_t i = (uint32_t)tid * 16u; i < 65536u; i += 4096u)
            *(uint4*)(smem + T_H0H + i) = z;
        const float4* x4 = (const float4*)(x + (size_t)row0 * 128);
        for (int e = tid; e < 128 * 32; e += THREADS) {
            int r = e >> 5, c4 = e & 31;
            float4 v = x4[r * 32 + c4];
            int c = c4 * 4;
            char* th = (char*)smem + ((c < 64) ? T_YH0 : T_YH1);
            char* tl = (char*)smem + ((c < 64) ? T_YL0 : T_YL1);
            uint32_t off = (uint32_t)r * 128u + (uint32_t)(c & 63) * 2u;
            st_hilo2(th, tl, off, v.x, v.y);
            st_hilo2(th, tl, off + 4, v.z, v.w);
        }
    }

    // ---- per-thread roles ----
    const int l4 = lane >> 2;           // row within 8
    const int ln = lane & 3;            // n-pair selector
    const int u0 = w * 8 + 2 * ln;      // this thread's unit pair (gates)

    // bias preload (acc-init values)
    float b0r[4][2], b1r[4][2], bfr[2][2];
#pragma unroll
    for (int v = 0; v < 4; ++v)
#pragma unroll
        for (int j = 0; j < 2; ++j) {
            b0r[v][j] = b0[v * 64 + u0 + j];
            b1r[v][j] = b1[v * 64 + u0 + j];
        }
#pragma unroll
    for (int v = 0; v < 2; ++v)
#pragma unroll
        for (int j = 0; j < 2; ++j)
            bfr[v][j] = bfc[w * 16 + v * 8 + 2 * ln + j];

    float c0s[32], c1s[32];
#pragma unroll
    for (int i = 0; i < 32; ++i) { c0s[i] = 0.0f; c1s[i] = 0.0f; }

    float acc[4][4][4];

    const __nv_bfloat16* wb = g_WB;

    // prologue: issue chunk 0
    {
        const char* src = (const char*)(wb + c_src[0]);
        uint32_t dst = sbase + SM_WBUF;
        for (uint32_t off = (uint32_t)tid * 16u; off < c_bytes[0]; off += 4096u)
            cp16(dst + off, src + off);
        cp_commit();
    }

#pragma unroll 1
    for (int t = 0; t < NSTEPS; ++t) {
#pragma unroll 1
        for (int c = 0; c < 24; ++c) {
            const int cc = c % 12;
            const int mp = c >= 12;
            const bool isFC = (cc >= 10);
            const int epi = (cc == 5) ? 1 : (cc == 9) ? 2 : (cc == 11) ? 3 : 0;
            const bool start = (cc == 0) | (cc == 6) | (cc == 10);

            __syncthreads();   // protects buffer (c+1)&1 + orders activation tile writes

            // issue next chunk (wrap to next step's chunk 0)
            const bool last = (t == NSTEPS - 1) && (c == 23);
            if (!last) {
                int nc = (c + 1) % 24, ncc = nc % 12;
                const char* src = (const char*)(wb + c_src[ncc]);
                uint32_t dst = sbase + SM_WBUF + (uint32_t)(nc & 1) * 32768u;
                uint32_t nbytes = c_bytes[ncc];
                for (uint32_t off = (uint32_t)tid * 16u; off < nbytes; off += 4096u)
                    cp16(dst + off, src + off);
                cp_commit();
                asm volatile("cp.async.wait_group 1;" ::: "memory");
            } else {
                asm volatile("cp.async.wait_group 0;" ::: "memory");
            }
            __syncthreads();   // chunk c visible to all

            // ---- acc init at phase start ----
            if (start) {
                if (isFC) {
#pragma unroll
                    for (int s = 0; s < 4; ++s)
#pragma unroll
                        for (int v = 0; v < 4; ++v)
#pragma unroll
                            for (int q = 0; q < 4; ++q)
                                acc[s][v][q] = (v < 2) ? bfr[v][q & 1] : 0.0f;
                } else {
                    const bool l0 = (cc == 0);
#pragma unroll
                    for (int s = 0; s < 4; ++s)
#pragma unroll
                        for (int v = 0; v < 4; ++v)
#pragma unroll
                            for (int q = 0; q < 4; ++q)
                                acc[s][v][q] = l0 ? b0r[v][q & 1] : b1r[v][q & 1];
                }
            }

            // ---- mma over this chunk (64 k) ----
            const uint32_t buf = sbase + SM_WBUF + (uint32_t)(c & 1) * 32768u;
            const uint32_t ahi = sbase + c_ahi[cc];
            const uint32_t alo_off = c_alo[cc];
            const bool haslo = (alo_off != NONE_OFF);
            const uint32_t alo = sbase + alo_off;
            const int nbase = isFC ? (w * 16) : (w * 32);
            const int arow_b = mp * 64 + (lane & 15);

#pragma unroll
            for (int k16 = 0; k16 < 4; ++k16) {
                const uint32_t colb = (uint32_t)(k16 * 32 + ((lane >> 4) << 4));
                // B fragments
                uint32_t bf[4][2];
                {
                    uint32_t r[4];
                    uint32_t bo = (uint32_t)(nbase + (lane & 15)) * 128u + colb;
                    ldm_x4(r, buf + SWZ128(bo));
                    bf[0][0] = r[0]; bf[1][0] = r[1]; bf[0][1] = r[2]; bf[1][1] = r[3];
                    if (!isFC) {
                        uint32_t bo2 = (uint32_t)(nbase + 16 + (lane & 15)) * 128u + colb;
                        ldm_x4(r, buf + SWZ128(bo2));
                        bf[2][0] = r[0]; bf[3][0] = r[1]; bf[2][1] = r[2]; bf[3][1] = r[3];
                    }
                }
                const int nt = isFC ? 2 : 4;
#pragma unroll
                for (int s = 0; s < 4; ++s) {
                    uint32_t ao = (uint32_t)(arow_b + s * 16) * 128u + colb;
                    uint32_t ah[4];
                    ldm_x4(ah, ahi + SWZ128(ao));
                    if (haslo) {
                        uint32_t al[4];
                        ldm_x4(al, alo + SWZ128(ao));
#pragma unroll
                        for (int v = 0; v < 4; ++v) {
                            if (v >= nt) break;
                            mma16816(acc[s][v], ah, bf[v]);
                            mma16816(acc[s][v], al, bf[v]);
                        }
                    } else {
#pragma unroll
                        for (int v = 0; v < 4; ++v) {
                            if (v >= nt) break;
                            mma16816(acc[s][v], ah, bf[v]);
                        }
                    }
                }
            }

            // ---- epilogues ----
            if (epi == 1 || epi == 2) {
                __syncthreads();   // all mma reads of H tile done before overwrite
                float* cst = (epi == 1) ? c0s : c1s;
                char* th = (char*)smem + ((epi == 1) ? T_H0H : T_H1H);
                char* tl = (char*)smem + ((epi == 1) ? T_H0L : T_H1L);
#pragma unroll
                for (int s = 0; s < 4; ++s)
#pragma unroll
                    for (int rh = 0; rh < 2; ++rh) {
                        float h2[2];
#pragma unroll
                        for (int j = 0; j < 2; ++j) {
                            float iv = sigm(acc[s][0][rh * 2 + j]);
                            float fv = sigm(acc[s][1][rh * 2 + j]);
                            float gv = tanh_fast(acc[s][2][rh * 2 + j]);
                            float ov = sigm(acc[s][3][rh * 2 + j]);
                            int ci = mp * 16 + s * 4 + rh * 2 + j;
                            float cv = fv * cst[ci] + iv * gv;
                            cst[ci] = cv;
                            h2[j] = ov * tanh_fast(cv);
                        }
                        int row = mp * 64 + s * 16 + l4 + rh * 8;
                        st_hilo2(th, tl, (uint32_t)row * 128u + (uint32_t)u0 * 2u,
                                 h2[0], h2[1]);
                    }
            } else if (epi == 3) {
                // FC epilogue: y = acc (+bias already), write gmem + Y tiles
                const size_t tb = (size_t)t * B_ROWS * DDIM;
#pragma unroll
                for (int s = 0; s < 4; ++s)
#pragma unroll
                    for (int rh = 0; rh < 2; ++rh) {
                        int row = mp * 64 + s * 16 + l4 + rh * 8;
                        float* ys = ystack ? (ystack + tb + (size_t)(row0 + row) * DDIM)
                                           : nullptr;
                        float* yl = (ylast && t == NSTEPS - 1)
                                        ? (ylast + (size_t)(row0 + row) * DDIM) : nullptr;
#pragma unroll
                        for (int v = 0; v < 2; ++v) {
                            int d = w * 16 + v * 8 + 2 * ln;
                            float y0 = acc[s][v][rh * 2 + 0];
                            float y1 = acc[s][v][rh * 2 + 1];
                            if (ys) { float2 p = make_float2(y0, y1); *(float2*)(ys + d) = p; }
                            if (yl) { float2 p = make_float2(y0, y1); *(float2*)(yl + d) = p; }
                            char* th = (char*)smem + ((d < 64) ? T_YH0 : T_YH1);
                            char* tl = (char*)smem + ((d < 64) ? T_YL0 : T_YL1);
                            st_hilo2(th, tl, (uint32_t)row * 128u + (uint32_t)(d & 63) * 2u,
                                     y0, y1);
                        }
                    }
            }
        }
    }
}

extern "C" void kernel_launch(void* const* d_in, const int* in_sizes, int n_in,
                              void* d_out, int out_size) {
    const float* x    = (const float*)d_in[0];
    const float* Wih0 = (const float*)d_in[1];
    const float* Whh0 = (const float*)d_in[2];
    const float* b0   = (const float*)d_in[3];
    const float* Wih1 = (const float*)d_in[4];
    const float* Whh1 = (const float*)d_in[5];
    const float* b1   = (const float*)d_in[6];
    const float* Wfc  = (const float*)d_in[7];
    const float* bfc  = (const float*)d_in[8];
    (void)in_sizes; (void)n_in;

    float* out = (float*)d_out;
    const long long BD = (long long)B_ROWS * DDIM;
    float* ylast  = nullptr;
    float* ystack = nullptr;
    if ((long long)out_size >= BD * (NSTEPS + 1)) {
        ylast  = out;
        ystack = out + BD;
    } else if ((long long)out_size >= BD * NSTEPS) {
        ystack = out;
    } else {
        ylast = out;
    }

    cudaFuncSetAttribute(lstm_hmma_kernel,
                         cudaFuncAttributeMaxDynamicSharedMemorySize, SM_TOTAL);

    prep_kernel<<<64, 256>>>(Wih0, Whh0, Wih1, Whh1, Wfc);
    lstm_hmma_kernel<<<B_ROWS / 128, THREADS, SM_TOTAL>>>(x, b0, b1, bfc, ystack, ylast);
}

// round 9
// speedup vs baseline: 2.1217x; 1.1745x over previous
#include <cuda_runtime.h>
#include <cuda_bf16.h>
#include <cstdint>
#include <cstddef>

#define B_ROWS 32768
#define DDIM   128
#define NSTEPS 32
#define THREADS 512
#define NONE_OFF 0xFFFFFFFFu

// ---------------- packed weight scratch: one big array ----------------
// [W0h 49152][W0l 49152][W1h 32768][W1l 32768][Wfh 8192][Wfl 8192] bf16 elems
// Each 16384-elem chunk = [256 n x 64 k], 128B rows, SW128 swizzled.
// Gate chunks use unit-interleaved n: n = (u>>3)*32 + g*8 + (u&7).
__device__ __align__(128) __nv_bfloat16 g_WB[180224];

#define SWZ128(o) ((o) ^ (((o) >> 3) & 0x70))

static __device__ __forceinline__ uint32_t smem_u32(const void* p) {
    uint32_t a;
    asm("{ .reg .u64 t; cvta.to.shared.u64 t, %1; cvt.u32.u64 %0, t; }" : "=r"(a) : "l"(p));
    return a;
}

// ---------------- mma / ldmatrix / cp.async ----------------
static __device__ __forceinline__ void ldm_x4(uint32_t* r, uint32_t addr) {
    asm volatile("ldmatrix.sync.aligned.m8n8.x4.shared.b16 {%0,%1,%2,%3}, [%4];"
                 : "=r"(r[0]), "=r"(r[1]), "=r"(r[2]), "=r"(r[3]) : "r"(addr));
}
static __device__ __forceinline__ void mma16816(float* c, const uint32_t* a, const uint32_t* b) {
    asm volatile(
        "mma.sync.aligned.m16n8k16.row.col.f32.bf16.bf16.f32 "
        "{%0,%1,%2,%3}, {%4,%5,%6,%7}, {%8,%9}, {%0,%1,%2,%3};"
        : "+f"(c[0]), "+f"(c[1]), "+f"(c[2]), "+f"(c[3])
        : "r"(a[0]), "r"(a[1]), "r"(a[2]), "r"(a[3]), "r"(b[0]), "r"(b[1]));
}
static __device__ __forceinline__ void cp16(uint32_t dst, const void* src) {
    asm volatile("cp.async.cg.shared.global [%0], [%1], 16;" :: "r"(dst), "l"(src));
}
static __device__ __forceinline__ void cp_commit() {
    asm volatile("cp.async.commit_group;" ::: "memory");
}

static __device__ __forceinline__ float sigm(float x) {
    return __fdividef(1.0f, 1.0f + __expf(-x));
}
static __device__ __forceinline__ float tanh_fast(float x) {
    float e = __expf(-2.0f * fabsf(x));
    float t = __fdividef(1.0f - e, 1.0f + e);
    return copysignf(t, x);
}

// ---------------- smem layout (byte offsets in dynamic smem) ----------------
#define T_YH0 0
#define T_YH1 16384
#define T_YL0 32768
#define T_YL1 49152
#define T_H0H 65536
#define T_H0L 81920
#define T_H1H 98304
#define T_H1L 114688
#define SM_WBUF 131072              /* 2 x 32KB stream buffers */
#define SM_B0   196608              /* 256 floats */
#define SM_B1   197632              /* 256 floats */
#define SM_BFC  198656              /* 128 floats */
#define SM_TOTAL 199168

// ---------------- per-step chunk sequence (12 chunks, both warp-groups) ----------------
__constant__ uint32_t c_src[12] = {
    0, 16384, 32768,          // L0 hi: k-blocks y0,y1,h0
    49152, 65536, 81920,      // L0 lo
    98304, 114688,            // L1 hi: h0,h1
    131072, 147456,           // L1 lo
    163840, 172032            // FC hi, lo
};
__constant__ uint32_t c_bytes[12] = {
    32768, 32768, 32768, 32768, 32768, 32768,
    32768, 32768, 32768, 32768, 16384, 16384
};
__constant__ uint32_t c_ahi[12] = {
    T_YH0, T_YH1, T_H0H, T_YH0, T_YH1, T_H0H,
    T_H0H, T_H1H, T_H0H, T_H1H, T_H1H, T_H1H
};
__constant__ uint32_t c_alo[12] = {
    T_YL0, T_YL1, T_H0L, NONE_OFF, NONE_OFF, NONE_OFF,
    T_H0L, T_H1L, NONE_OFF, NONE_OFF, T_H1L, NONE_OFF
};

// ---------------- weight prep: split + pack + swizzle ----------------
static __device__ __forceinline__ void wpack(uint32_t hi_off, uint32_t lo_off,
                                             int n, int kk, float w) {
    uint32_t sw = SWZ128((uint32_t)n * 128u + (uint32_t)kk * 2u) >> 1;
    __nv_bfloat16 h = __float2bfloat16(w);
    g_WB[hi_off + sw] = h;
    g_WB[lo_off + sw] = __float2bfloat16(w - __bfloat162float(h));
}

__global__ void prep_kernel(const float* __restrict__ Wih0, const float* __restrict__ Whh0,
                            const float* __restrict__ Wih1, const float* __restrict__ Whh1,
                            const float* __restrict__ Wfc) {
    int i = blockIdx.x * blockDim.x + threadIdx.x;
    int stride = gridDim.x * blockDim.x;
    for (int idx = i; idx < 3 * 16384; idx += stride) {
        int ch = idx >> 14, e = idx & 16383, n = e >> 6, kk = e & 63;
        int g = (n >> 3) & 3, u = ((n >> 5) << 3) | (n & 7);
        float w = (ch < 2) ? Wih0[(g * 64 + u) * 128 + ch * 64 + kk]
                           : Whh0[(g * 64 + u) * 64 + kk];
        wpack(0 + ch * 16384, 49152 + ch * 16384, n, kk, w);
    }
    for (int idx = i; idx < 2 * 16384; idx += stride) {
        int ch = idx >> 14, e = idx & 16383, n = e >> 6, kk = e & 63;
        int g = (n >> 3) & 3, u = ((n >> 5) << 3) | (n & 7);
        float w = (ch == 0) ? Wih1[(g * 64 + u) * 64 + kk]
                            : Whh1[(g * 64 + u) * 64 + kk];
        wpack(98304 + ch * 16384, 131072 + ch * 16384, n, kk, w);
    }
    for (int idx = i; idx < 8192; idx += stride) {
        int n = idx >> 6, kk = idx & 63;
        wpack(163840, 172032, n, kk, Wfc[n * 64 + kk]);
    }
}

// ---------------- activation hi/lo store ----------------
static __device__ __forceinline__ void st_hilo2(char* th, char* tl, uint32_t off,
                                                float a, float b) {
    uint32_t sw = SWZ128(off);
    __nv_bfloat16 ah = __float2bfloat16(a), bh = __float2bfloat16(b);
    __nv_bfloat162 hp; hp.x = ah; hp.y = bh;
    *(__nv_bfloat162*)(th + sw) = hp;
    __nv_bfloat162 lp;
    lp.x = __float2bfloat16(a - __bfloat162float(ah));
    lp.y = __float2bfloat16(b - __bfloat162float(bh));
    *(__nv_bfloat162*)(tl + sw) = lp;
}

// ---------------- main kernel ----------------
extern __shared__ char smem[];

__global__ __launch_bounds__(THREADS, 1)
void lstm_hmma_kernel(const float* __restrict__ x,
                      const float* __restrict__ b0, const float* __restrict__ b1,
                      const float* __restrict__ bfc,
                      float* __restrict__ ystack, float* __restrict__ ylast) {
    const uint32_t sbase = smem_u32(smem);
    const int tid = threadIdx.x, lane = tid & 31, w = tid >> 5;
    const int wg = w >> 3;              // warp-group: row half (0: rows 0-63, 1: 64-127)
    const int wl = w & 7;               // n-position within group
    const int row0 = blockIdx.x * 128;

    // ---- init: biases -> smem, x -> Y tiles, zero H tiles ----
    if (tid < 256) {
        ((float*)(smem + SM_B0))[tid] = b0[tid];
        ((float*)(smem + SM_B1))[tid] = b1[tid];
        if (tid < 128) ((float*)(smem + SM_BFC))[tid] = bfc[tid];
    }
    {
        uint4 z = make_uint4(0, 0, 0, 0);
        for (uint32_t i = (uint32_t)tid * 16u; i < 65536u; i += THREADS * 16u)
            *(uint4*)(smem + T_H0H + i) = z;
        const float4* x4 = (const float4*)(x + (size_t)row0 * 128);
        for (int e = tid; e < 128 * 32; e += THREADS) {
            int r = e >> 5, c4 = e & 31;
            float4 v = x4[r * 32 + c4];
            int c = c4 * 4;
            char* th = (char*)smem + ((c < 64) ? T_YH0 : T_YH1);
            char* tl = (char*)smem + ((c < 64) ? T_YL0 : T_YL1);
            uint32_t off = (uint32_t)r * 128u + (uint32_t)(c & 63) * 2u;
            st_hilo2(th, tl, off, v.x, v.y);
            st_hilo2(th, tl, off + 4, v.z, v.w);
        }
    }

    // ---- per-thread roles ----
    const int l4 = lane >> 2;            // row within 8
    const int ln = lane & 3;             // n-pair selector
    const int u0 = wl * 8 + 2 * ln;      // unit pair (gates)
    const uint32_t xm = (uint32_t)(lane & 7) << 4;   // lane-constant swizzle mask
    const int arow = wg * 64 + (lane & 15);

    const float* b0s  = (const float*)(smem + SM_B0);
    const float* b1s  = (const float*)(smem + SM_B1);
    const float* bfcs = (const float*)(smem + SM_BFC);

    float c0s[16], c1s[16];
#pragma unroll
    for (int i = 0; i < 16; ++i) { c0s[i] = 0.0f; c1s[i] = 0.0f; }

    float acc[4][4][4];

    // prologue: issue chunk 0
    {
        const char* src = (const char*)(g_WB + c_src[0]);
        uint32_t dst = sbase + SM_WBUF;
        for (uint32_t off = (uint32_t)tid * 16u; off < c_bytes[0]; off += THREADS * 16u)
            cp16(dst + off, src + off);
        cp_commit();
    }

#pragma unroll 1
    for (int t = 0; t < NSTEPS; ++t) {
#pragma unroll 1
        for (int c = 0; c < 12; ++c) {
            const bool isFC = (c >= 10);
            const int epi = (c == 5) ? 1 : (c == 9) ? 2 : (c == 11) ? 3 : 0;
            const bool start = (c == 0) | (c == 6) | (c == 10);

            __syncthreads();   // buffer (c+1)&1 free + activation-tile writes ordered

            // issue next chunk (wrap to next step's chunk 0)
            const bool last = (t == NSTEPS - 1) && (c == 11);
            if (!last) {
                int nc = (c + 1) % 12;
                const char* src = (const char*)(g_WB + c_src[nc]);
                uint32_t dst = sbase + SM_WBUF + (uint32_t)(~c & 1) * 32768u;
                uint32_t nbytes = c_bytes[nc];
                for (uint32_t off = (uint32_t)tid * 16u; off < nbytes; off += THREADS * 16u)
                    cp16(dst + off, src + off);
                cp_commit();
                asm volatile("cp.async.wait_group 1;" ::: "memory");
            } else {
                asm volatile("cp.async.wait_group 0;" ::: "memory");
            }
            __syncthreads();   // chunk c visible to all warps

            // ---- acc init at phase start (biases from smem) ----
            if (start) {
                if (isFC) {
                    float bb[2][2];
#pragma unroll
                    for (int v = 0; v < 2; ++v)
#pragma unroll
                        for (int j = 0; j < 2; ++j)
                            bb[v][j] = bfcs[wl * 16 + v * 8 + 2 * ln + j];
#pragma unroll
                    for (int s = 0; s < 4; ++s)
#pragma unroll
                        for (int v = 0; v < 4; ++v)
#pragma unroll
                            for (int q = 0; q < 4; ++q)
                                acc[s][v][q] = (v < 2) ? bb[v][q & 1] : 0.0f;
                } else {
                    const float* bs = (c == 0) ? b0s : b1s;
                    float bb[4][2];
#pragma unroll
                    for (int v = 0; v < 4; ++v)
#pragma unroll
                        for (int j = 0; j < 2; ++j)
                            bb[v][j] = bs[v * 64 + u0 + j];
#pragma unroll
                    for (int s = 0; s < 4; ++s)
#pragma unroll
                        for (int v = 0; v < 4; ++v)
#pragma unroll
                            for (int q = 0; q < 4; ++q)
                                acc[s][v][q] = bb[v][q & 1];
                }
            }

            // ---- mma over this chunk (64 k) ----
            const uint32_t buf = sbase + SM_WBUF + (uint32_t)(c & 1) * 32768u;
            const uint32_t ahi = sbase + c_ahi[c];
            const uint32_t alo_off = c_alo[c];
            const bool haslo = (alo_off != NONE_OFF);
            const uint32_t alo = sbase + alo_off;
            const int nb = (isFC ? wl * 16 : wl * 32) + (lane & 15);
            const uint32_t brow = buf + (uint32_t)nb * 128u;
            const uint32_t hi16 = (uint32_t)((lane >> 4) << 4);

#pragma unroll
            for (int k16 = 0; k16 < 4; ++k16) {
                const uint32_t cx = ((uint32_t)(k16 * 32) + hi16) ^ xm;
                // B fragments
                uint32_t bfr[4][2];
                {
                    uint32_t r[4];
                    ldm_x4(r, brow + cx);
                    bfr[0][0] = r[0]; bfr[1][0] = r[1]; bfr[0][1] = r[2]; bfr[1][1] = r[3];
                    if (!isFC) {
                        ldm_x4(r, brow + 2048u + cx);   // +16 n rows
                        bfr[2][0] = r[0]; bfr[3][0] = r[1]; bfr[2][1] = r[2]; bfr[3][1] = r[3];
                    }
                }
                const int nt = isFC ? 2 : 4;
#pragma unroll
                for (int s = 0; s < 4; ++s) {
                    const uint32_t aoff = (uint32_t)(arow + s * 16) * 128u + cx;
                    uint32_t ah[4];
                    ldm_x4(ah, ahi + aoff);
                    if (haslo) {
                        uint32_t al[4];
                        ldm_x4(al, alo + aoff);
#pragma unroll
                        for (int v = 0; v < 4; ++v) {
                            if (v >= nt) break;
                            mma16816(acc[s][v], ah, bfr[v]);
                            mma16816(acc[s][v], al, bfr[v]);
                        }
                    } else {
#pragma unroll
                        for (int v = 0; v < 4; ++v) {
                            if (v >= nt) break;
                            mma16816(acc[s][v], ah, bfr[v]);
                        }
                    }
                }
            }

            // ---- epilogues ----
            if (epi == 1 || epi == 2) {
                __syncthreads();   // all mma reads of H tile done before overwrite
                float* cst = (epi == 1) ? c0s : c1s;
                char* th = (char*)smem + ((epi == 1) ? T_H0H : T_H1H);
                char* tl = (char*)smem + ((epi == 1) ? T_H0L : T_H1L);
#pragma unroll
                for (int s = 0; s < 4; ++s)
#pragma unroll
                    for (int rh = 0; rh < 2; ++rh) {
                        float h2[2];
#pragma unroll
                        for (int j = 0; j < 2; ++j) {
                            float iv = sigm(acc[s][0][rh * 2 + j]);
                            float fv = sigm(acc[s][1][rh * 2 + j]);
                            float gv = tanh_fast(acc[s][2][rh * 2 + j]);
                            float ov = sigm(acc[s][3][rh * 2 + j]);
                            int ci = s * 4 + rh * 2 + j;
                            float cv = fv * cst[ci] + iv * gv;
                            cst[ci] = cv;
                            h2[j] = ov * tanh_fast(cv);
                        }
                        int row = wg * 64 + s * 16 + l4 + rh * 8;
                        st_hilo2(th, tl, (uint32_t)row * 128u + (uint32_t)u0 * 2u,
                                 h2[0], h2[1]);
                    }
            } else if (epi == 3) {
                // FC epilogue: y = acc (+bias already), write gmem + Y tiles
                const size_t tb = (size_t)t * B_ROWS * DDIM;
#pragma unroll
                for (int s = 0; s < 4; ++s)
#pragma unroll
                    for (int rh = 0; rh < 2; ++rh) {
                        int row = wg * 64 + s * 16 + l4 + rh * 8;
                        float* ys = ystack ? (ystack + tb + (size_t)(row0 + row) * DDIM)
                                           : nullptr;
                        float* yl = (ylast && t == NSTEPS - 1)
                                        ? (ylast + (size_t)(row0 + row) * DDIM) : nullptr;
#pragma unroll
                        for (int v = 0; v < 2; ++v) {
                            int d = wl * 16 + v * 8 + 2 * ln;
                            float y0 = acc[s][v][rh * 2 + 0];
                            float y1 = acc[s][v][rh * 2 + 1];
                            if (ys) { float2 p = make_float2(y0, y1); *(float2*)(ys + d) = p; }
                            if (yl) { float2 p = make_float2(y0, y1); *(float2*)(yl + d) = p; }
                            char* th = (char*)smem + ((d < 64) ? T_YH0 : T_YH1);
                            char* tl = (char*)smem + ((d < 64) ? T_YL0 : T_YL1);
                            st_hilo2(th, tl, (uint32_t)row * 128u + (uint32_t)(d & 63) * 2u,
                                     y0, y1);
                        }
                    }
            }
        }
    }
}

extern "C" void kernel_launch(void* const* d_in, const int* in_sizes, int n_in,
                              void* d_out, int out_size) {
    const float* x    = (const float*)d_in[0];
    const float* Wih0 = (const float*)d_in[1];
    const float* Whh0 = (const float*)d_in[2];
    const float* b0   = (const float*)d_in[3];
    const float* Wih1 = (const float*)d_in[4];
    const float* Whh1 = (const float*)d_in[5];
    const float* b1   = (const float*)d_in[6];
    const float* Wfc  = (const float*)d_in[7];
    const float* bfc  = (const float*)d_in[8];
    (void)in_sizes; (void)n_in;

    float* out = (float*)d_out;
    const long long BD = (long long)B_ROWS * DDIM;
    float* ylast  = nullptr;
    float* ystack = nullptr;
    if ((long long)out_size >= BD * (NSTEPS + 1)) {
        ylast  = out;
        ystack = out + BD;
    } else if ((long long)out_size >= BD * NSTEPS) {
        ystack = out;
    } else {
        ylast = out;
    }

    cudaFuncSetAttribute(lstm_hmma_kernel,
                         cudaFuncAttributeMaxDynamicSharedMemorySize, SM_TOTAL);

    prep_kernel<<<64, 256>>>(Wih0, Whh0, Wih1, Whh1, Wfc);
    lstm_hmma_kernel<<<B_ROWS / 128, THREADS, SM_TOTAL>>>(x, b0, b1, bfc, ystack, ylast);
}

// round 11
// speedup vs baseline: 3.1854x; 1.5013x over previous
#include <cuda_runtime.h>
#include <cuda_bf16.h>
#include <cstdint>
#include <cstddef>

#define B_ROWS 32768
#define DDIM   128
#define NSTEPS 32
#define THREADS 512

// ---------------- packed weight scratch ----------------
// [W0h 49152][W1h 32768][Wfh 8192][Wfl 8192] bf16 elems (+ slack).
// Each 16384-elem chunk = [256 n x 64 k], 128B rows, SW128 swizzled.
// Gate chunks use unit-interleaved n: n = (u>>3)*32 + g*8 + (u&7).
// FC hi at 81920, FC lo at 90112 (contiguous 32KB pair).
__device__ __align__(128) __nv_bfloat16 g_WB[98304];

#define SWZ128(o) ((o) ^ (((o) >> 3) & 0x70))

static __device__ __forceinline__ uint32_t smem_u32(const void* p) {
    uint32_t a;
    asm("{ .reg .u64 t; cvta.to.shared.u64 t, %1; cvt.u32.u64 %0, t; }" : "=r"(a) : "l"(p));
    return a;
}

// ---------------- mma / ldmatrix / cp.async ----------------
static __device__ __forceinline__ void ldm_x4(uint32_t* r, uint32_t addr) {
    asm volatile("ldmatrix.sync.aligned.m8n8.x4.shared.b16 {%0,%1,%2,%3}, [%4];"
                 : "=r"(r[0]), "=r"(r[1]), "=r"(r[2]), "=r"(r[3]) : "r"(addr));
}
static __device__ __forceinline__ void mma16816(float* c, const uint32_t* a, const uint32_t* b) {
    asm volatile(
        "mma.sync.aligned.m16n8k16.row.col.f32.bf16.bf16.f32 "
        "{%0,%1,%2,%3}, {%4,%5,%6,%7}, {%8,%9}, {%0,%1,%2,%3};"
        : "+f"(c[0]), "+f"(c[1]), "+f"(c[2]), "+f"(c[3])
        : "r"(a[0]), "r"(a[1]), "r"(a[2]), "r"(a[3]), "r"(b[0]), "r"(b[1]));
}
static __device__ __forceinline__ void cp16(uint32_t dst, const void* src) {
    asm volatile("cp.async.cg.shared.global [%0], [%1], 16;" :: "r"(dst), "l"(src));
}
static __device__ __forceinline__ void cp_commit() {
    asm volatile("cp.async.commit_group;" ::: "memory");
}

static __device__ __forceinline__ float sigm(float x) {
    return __fdividef(1.0f, 1.0f + __expf(-x));
}
static __device__ __forceinline__ float tanh_fast(float x) {
    float e = __expf(-2.0f * fabsf(x));
    float t = __fdividef(1.0f - e, 1.0f + e);
    return copysignf(t, x);
}

// ---------------- smem layout (byte offsets in dynamic smem) ----------------
#define T_YH0 0
#define T_YH1 16384
#define T_YL0 32768
#define T_YL1 49152
#define T_H0H 65536
#define T_H0L 81920
#define T_H1H 98304
#define T_H1L 114688
#define SM_WBUF 131072              /* 2 x 32KB stream buffers */
#define SM_B0   196608              /* 256 floats */
#define SM_B1   197632              /* 256 floats */
#define SM_BFC  198656              /* 128 floats */
#define SM_TOTAL 199168

// ---------------- per-step chunk sequence (6 chunks; all 32KB) ----------------
// 0: W0h k=y0   A=Y0 (hi+lo)
// 1: W0h k=y1   A=Y1 (hi+lo)
// 2: W0h k=h0   A=H0 (hi+lo)   -> L0 epilogue (writes H0)
// 3: W1h k=h0   A=H0 (hi+lo)
// 4: W1h k=h1   A=H1 (hi+lo)   -> L1 epilogue (writes H1)
// 5: Wf hi+lo   A=H1 (hi+lo)   -> FC epilogue (3-term, writes Y + gmem)
__constant__ uint32_t c_src[6] = { 0, 16384, 32768, 49152, 65536, 81920 };
__constant__ uint32_t c_ahi[6] = { T_YH0, T_YH1, T_H0H, T_H0H, T_H1H, T_H1H };
__constant__ uint32_t c_alo[6] = { T_YL0, T_YL1, T_H0L, T_H0L, T_H1L, T_H1L };

// ---------------- weight prep ----------------
__global__ void prep_kernel(const float* __restrict__ Wih0, const float* __restrict__ Whh0,
                            const float* __restrict__ Wih1, const float* __restrict__ Whh1,
                            const float* __restrict__ Wfc) {
    int i = blockIdx.x * blockDim.x + threadIdx.x;
    int stride = gridDim.x * blockDim.x;
    // L0 hi chunks (plain bf16 weights), gate-interleaved n
    for (int idx = i; idx < 3 * 16384; idx += stride) {
        int ch = idx >> 14, e = idx & 16383, n = e >> 6, kk = e & 63;
        int g = (n >> 3) & 3, u = ((n >> 5) << 3) | (n & 7);
        float w = (ch < 2) ? Wih0[(g * 64 + u) * 128 + ch * 64 + kk]
                           : Whh0[(g * 64 + u) * 64 + kk];
        uint32_t sw = SWZ128((uint32_t)n * 128u + (uint32_t)kk * 2u) >> 1;
        g_WB[ch * 16384 + sw] = __float2bfloat16(w);
    }
    // L1 hi chunks
    for (int idx = i; idx < 2 * 16384; idx += stride) {
        int ch = idx >> 14, e = idx & 16383, n = e >> 6, kk = e & 63;
        int g = (n >> 3) & 3, u = ((n >> 5) << 3) | (n & 7);
        float w = (ch == 0) ? Wih1[(g * 64 + u) * 64 + kk]
                            : Whh1[(g * 64 + u) * 64 + kk];
        uint32_t sw = SWZ128((uint32_t)n * 128u + (uint32_t)kk * 2u) >> 1;
        g_WB[49152 + ch * 16384 + sw] = __float2bfloat16(w);
    }
    // FC: hi at 81920, lo at 90112 (3-term kept for output accuracy)
    for (int idx = i; idx < 8192; idx += stride) {
        int n = idx >> 6, kk = idx & 63;
        float w = Wfc[n * 64 + kk];
        uint32_t sw = SWZ128((uint32_t)n * 128u + (uint32_t)kk * 2u) >> 1;
        __nv_bfloat16 h = __float2bfloat16(w);
        g_WB[81920 + sw] = h;
        g_WB[90112 + sw] = __float2bfloat16(w - __bfloat162float(h));
    }
}

// ---------------- activation hi/lo store ----------------
static __device__ __forceinline__ void st_hilo2(char* th, char* tl, uint32_t off,
                                                float a, float b) {
    uint32_t sw = SWZ128(off);
    __nv_bfloat16 ah = __float2bfloat16(a), bh = __float2bfloat16(b);
    __nv_bfloat162 hp; hp.x = ah; hp.y = bh;
    *(__nv_bfloat162*)(th + sw) = hp;
    __nv_bfloat162 lp;
    lp.x = __float2bfloat16(a - __bfloat162float(ah));
    lp.y = __float2bfloat16(b - __bfloat162float(bh));
    *(__nv_bfloat162*)(tl + sw) = lp;
}

// ---------------- main kernel ----------------
extern __shared__ char smem[];

__global__ __launch_bounds__(THREADS, 1)
void lstm_hmma_kernel(const float* __restrict__ x,
                      const float* __restrict__ b0, const float* __restrict__ b1,
                      const float* __restrict__ bfc,
                      float* __restrict__ ystack, float* __restrict__ ylast) {
    const uint32_t sbase = smem_u32(smem);
    const int tid = threadIdx.x, lane = tid & 31, w = tid >> 5;
    const int wg = w >> 3;              // warp-group: row half (0: rows 0-63, 1: 64-127)
    const int wl = w & 7;               // n-position within group
    const int row0 = blockIdx.x * 128;

    // ---- init: biases -> smem, x -> Y tiles, zero H tiles ----
    if (tid < 256) {
        ((float*)(smem + SM_B0))[tid] = b0[tid];
        ((float*)(smem + SM_B1))[tid] = b1[tid];
        if (tid < 128) ((float*)(smem + SM_BFC))[tid] = bfc[tid];
    }
    {
        uint4 z = make_uint4(0, 0, 0, 0);
        for (uint32_t i = (uint32_t)tid * 16u; i < 65536u; i += THREADS * 16u)
            *(uint4*)(smem + T_H0H + i) = z;
        const float4* x4 = (const float4*)(x + (size_t)row0 * 128);
        for (int e = tid; e < 128 * 32; e += THREADS) {
            int r = e >> 5, c4 = e & 31;
            float4 v = x4[r * 32 + c4];
            int c = c4 * 4;
            char* th = (char*)smem + ((c < 64) ? T_YH0 : T_YH1);
            char* tl = (char*)smem + ((c < 64) ? T_YL0 : T_YL1);
            uint32_t off = (uint32_t)r * 128u + (uint32_t)(c & 63) * 2u;
            st_hilo2(th, tl, off, v.x, v.y);
            st_hilo2(th, tl, off + 4, v.z, v.w);
        }
    }

    // ---- per-thread roles ----
    const int l4 = lane >> 2;            // row within 8
    const int ln = lane & 3;             // n-pair selector
    const int u0 = wl * 8 + 2 * ln;      // unit pair (gates)
    const uint32_t xm = (uint32_t)(lane & 7) << 4;   // lane-constant swizzle mask
    const int arow = wg * 64 + (lane & 15);

    const float* b0s  = (const float*)(smem + SM_B0);
    const float* b1s  = (const float*)(smem + SM_B1);
    const float* bfcs = (const float*)(smem + SM_BFC);

    float c0s[16], c1s[16];
#pragma unroll
    for (int i = 0; i < 16; ++i) { c0s[i] = 0.0f; c1s[i] = 0.0f; }

    float acc[4][4][4];

    // prologue: issue chunk 0
    {
        const char* src = (const char*)(g_WB + c_src[0]);
        uint32_t dst = sbase + SM_WBUF;
        for (uint32_t off = (uint32_t)tid * 16u; off < 32768u; off += THREADS * 16u)
            cp16(dst + off, src + off);
        cp_commit();
    }

#pragma unroll 1
    for (int t = 0; t < NSTEPS; ++t) {
#pragma unroll 1
        for (int c = 0; c < 6; ++c) {
            const bool isFC = (c == 5);
            const int epi = (c == 2) ? 1 : (c == 4) ? 2 : (c == 5) ? 3 : 0;
            const bool start = (c == 0) | (c == 3) | (c == 5);

            __syncthreads();   // buffer (c+1)&1 free + activation-tile writes ordered

            // issue next chunk (wrap to next step's chunk 0)
            const bool last = (t == NSTEPS - 1) && (c == 5);
            if (!last) {
                int nc = (c + 1) % 6;
                const char* src = (const char*)(g_WB + c_src[nc]);
                uint32_t dst = sbase + SM_WBUF + (uint32_t)(~c & 1) * 32768u;
                for (uint32_t off = (uint32_t)tid * 16u; off < 32768u; off += THREADS * 16u)
                    cp16(dst + off, src + off);
                cp_commit();
                asm volatile("cp.async.wait_group 1;" ::: "memory");
            } else {
                asm volatile("cp.async.wait_group 0;" ::: "memory");
            }
            __syncthreads();   // chunk c visible to all warps

            // ---- acc init at phase start (biases from smem) ----
            if (start) {
                if (isFC) {
                    float bb[2][2];
#pragma unroll
                    for (int v = 0; v < 2; ++v)
#pragma unroll
                        for (int j = 0; j < 2; ++j)
                            bb[v][j] = bfcs[wl * 16 + v * 8 + 2 * ln + j];
#pragma unroll
                    for (int s = 0; s < 4; ++s)
#pragma unroll
                        for (int v = 0; v < 4; ++v)
#pragma unroll
                            for (int q = 0; q < 4; ++q)
                                acc[s][v][q] = (v < 2) ? bb[v][q & 1] : 0.0f;
                } else {
                    const float* bs = (c == 0) ? b0s : b1s;
                    float bb[4][2];
#pragma unroll
                    for (int v = 0; v < 4; ++v)
#pragma unroll
                        for (int j = 0; j < 2; ++j)
                            bb[v][j] = bs[v * 64 + u0 + j];
#pragma unroll
                    for (int s = 0; s < 4; ++s)
#pragma unroll
                        for (int v = 0; v < 4; ++v)
#pragma unroll
                            for (int q = 0; q < 4; ++q)
                                acc[s][v][q] = bb[v][q & 1];
                }
            }

            // ---- mma over this chunk (64 k) ----
            const uint32_t buf = sbase + SM_WBUF + (uint32_t)(c & 1) * 32768u;
            const uint32_t ahi = sbase + c_ahi[c];
            const uint32_t alo = sbase + c_alo[c];
            const int nb = (isFC ? wl * 16 : wl * 32) + (lane & 15);
            const uint32_t brow = buf + (uint32_t)nb * 128u;
            const uint32_t hi16 = (uint32_t)((lane >> 4) << 4);

#pragma unroll
            for (int k16 = 0; k16 < 4; ++k16) {
                const uint32_t cx = ((uint32_t)(k16 * 32) + hi16) ^ xm;
                // B fragments: gates -> 32 n rows (2 ldm); FC -> 16 hi rows + 16 lo rows
                uint32_t bfr[4][2];
                {
                    uint32_t r[4];
                    ldm_x4(r, brow + cx);
                    bfr[0][0] = r[0]; bfr[1][0] = r[1]; bfr[0][1] = r[2]; bfr[1][1] = r[3];
                    ldm_x4(r, brow + (isFC ? 16384u : 2048u) + cx);
                    bfr[2][0] = r[0]; bfr[3][0] = r[1]; bfr[2][1] = r[2]; bfr[3][1] = r[3];
                }
#pragma unroll
                for (int s = 0; s < 4; ++s) {
                    const uint32_t aoff = (uint32_t)(arow + s * 16) * 128u + cx;
                    uint32_t ah[4], al[4];
                    ldm_x4(ah, ahi + aoff);
                    ldm_x4(al, alo + aoff);
                    if (isFC) {
#pragma unroll
                        for (int v = 0; v < 2; ++v) {
                            mma16816(acc[s][v], ah, bfr[v]);
                            mma16816(acc[s][v], al, bfr[v]);
                            mma16816(acc[s][v], ah, bfr[v + 2]);   // hi-A x lo-W
                        }
                    } else {
#pragma unroll
                        for (int v = 0; v < 4; ++v) {
                            mma16816(acc[s][v], ah, bfr[v]);
                            mma16816(acc[s][v], al, bfr[v]);
                        }
                    }
                }
            }

            // ---- epilogues ----
            if (epi == 1 || epi == 2) {
                __syncthreads();   // all mma reads of H tile done before overwrite
                float* cst = (epi == 1) ? c0s : c1s;
                char* th = (char*)smem + ((epi == 1) ? T_H0H : T_H1H);
                char* tl = (char*)smem + ((epi == 1) ? T_H0L : T_H1L);
#pragma unroll
                for (int s = 0; s < 4; ++s)
#pragma unroll
                    for (int rh = 0; rh < 2; ++rh) {
                        float h2[2];
#pragma unroll
                        for (int j = 0; j < 2; ++j) {
                            float iv = sigm(acc[s][0][rh * 2 + j]);
                            float fv = sigm(acc[s][1][rh * 2 + j]);
                            float gv = tanh_fast(acc[s][2][rh * 2 + j]);
                            float ov = sigm(acc[s][3][rh * 2 + j]);
                            int ci = s * 4 + rh * 2 + j;
                            float cv = fv * cst[ci] + iv * gv;
                            cst[ci] = cv;
                            h2[j] = ov * tanh_fast(cv);
                        }
                        int row = wg * 64 + s * 16 + l4 + rh * 8;
                        st_hilo2(th, tl, (uint32_t)row * 128u + (uint32_t)u0 * 2u,
                                 h2[0], h2[1]);
                    }
            } else if (epi == 3) {
                // FC epilogue: y = acc (+bias already), write gmem + Y tiles
                const size_t tb = (size_t)t * B_ROWS * DDIM;
#pragma unroll
                for (int s = 0; s < 4; ++s)
#pragma unroll
                    for (int rh = 0; rh < 2; ++rh) {
                        int row = wg * 64 + s * 16 + l4 + rh * 8;
                        float* ys = ystack ? (ystack + tb + (size_t)(row0 + row) * DDIM)
                                           : nullptr;
                        float* yl = (ylast && t == NSTEPS - 1)
                                        ? (ylast + (size_t)(row0 + row) * DDIM) : nullptr;
#pragma unroll
                        for (int v = 0; v < 2; ++v) {
                            int d = wl * 16 + v * 8 + 2 * ln;
                            float y0 = acc[s][v][rh * 2 + 0];
                            float y1 = acc[s][v][rh * 2 + 1];
                            if (ys) { float2 p = make_float2(y0, y1); *(float2*)(ys + d) = p; }
                            if (yl) { float2 p = make_float2(y0, y1); *(float2*)(yl + d) = p; }
                            char* th = (char*)smem + ((d < 64) ? T_YH0 : T_YH1);
                            char* tl = (char*)smem + ((d < 64) ? T_YL0 : T_YL1);
                            st_hilo2(th, tl, (uint32_t)row * 128u + (uint32_t)(d & 63) * 2u,
                                     y0, y1);
                        }
                    }
            }
        }
    }
}

extern "C" void kernel_launch(void* const* d_in, const int* in_sizes, int n_in,
                              void* d_out, int out_size) {
    const float* x    = (const float*)d_in[0];
    const float* Wih0 = (const float*)d_in[1];
    const float* Whh0 = (const float*)d_in[2];
    const float* b0   = (const float*)d_in[3];
    const float* Wih1 = (const float*)d_in[4];
    const float* Whh1 = (const float*)d_in[5];
    const float* b1   = (const float*)d_in[6];
    const float* Wfc  = (const float*)d_in[7];
    const float* bfc  = (const float*)d_in[8];
    (void)in_sizes; (void)n_in;

    float* out = (float*)d_out;
    const long long BD = (long long)B_ROWS * DDIM;
    float* ylast  = nullptr;
    float* ystack = nullptr;
    if ((long long)out_size >= BD * (NSTEPS + 1)) {
        ylast  = out;
        ystack = out + BD;
    } else if ((long long)out_size >= BD * NSTEPS) {
        ystack = out;
    } else {
        ylast = out;
    }

    cudaFuncSetAttribute(lstm_hmma_kernel,
                         cudaFuncAttributeMaxDynamicSharedMemorySize, SM_TOTAL);

    prep_kernel<<<64, 256>>>(Wih0, Whh0, Wih1, Whh1, Wfc);
    lstm_hmma_kernel<<<B_ROWS / 128, THREADS, SM_TOTAL>>>(x, b0, b1, bfc, ystack, ylast);
}

// round 12
// speedup vs baseline: 4.4886x; 1.4091x over previous
#include <cuda_runtime.h>
#include <cuda_bf16.h>
#include <cstdint>
#include <cstddef>

#define B_ROWS 32768
#define DDIM   128
#define NSTEPS 32
#define THREADS 512

// ---------------- packed weight scratch ----------------
// [W0h 49152][W1h 32768][Wfh 8192][Wfl 8192] bf16 elems (+ slack).
// Each 16384-elem chunk = [256 n x 64 k], 128B rows, SW128 swizzled.
// Gate chunks use unit-interleaved n: n = (u>>3)*32 + g*8 + (u&7).
// FC hi at 81920, FC lo at 90112 (contiguous 32KB pair).
__device__ __align__(128) __nv_bfloat16 g_WB[98304];

#define SWZ128(o) ((o) ^ (((o) >> 3) & 0x70))

static __device__ __forceinline__ uint32_t smem_u32(const void* p) {
    uint32_t a;
    asm("{ .reg .u64 t; cvta.to.shared.u64 t, %1; cvt.u32.u64 %0, t; }" : "=r"(a) : "l"(p));
    return a;
}

// ---------------- mma / ldmatrix / cp.async ----------------
static __device__ __forceinline__ void ldm_x4(uint32_t* r, uint32_t addr) {
    asm volatile("ldmatrix.sync.aligned.m8n8.x4.shared.b16 {%0,%1,%2,%3}, [%4];"
                 : "=r"(r[0]), "=r"(r[1]), "=r"(r[2]), "=r"(r[3]) : "r"(addr));
}
static __device__ __forceinline__ void mma16816(float* c, const uint32_t* a, const uint32_t* b) {
    asm volatile(
        "mma.sync.aligned.m16n8k16.row.col.f32.bf16.bf16.f32 "
        "{%0,%1,%2,%3}, {%4,%5,%6,%7}, {%8,%9}, {%0,%1,%2,%3};"
        : "+f"(c[0]), "+f"(c[1]), "+f"(c[2]), "+f"(c[3])
        : "r"(a[0]), "r"(a[1]), "r"(a[2]), "r"(a[3]), "r"(b[0]), "r"(b[1]));
}
static __device__ __forceinline__ void cp16(uint32_t dst, const void* src) {
    asm volatile("cp.async.cg.shared.global [%0], [%1], 16;" :: "r"(dst), "l"(src));
}
static __device__ __forceinline__ void cp_commit() {
    asm volatile("cp.async.commit_group;" ::: "memory");
}

static __device__ __forceinline__ float sigm(float x) {
    return __fdividef(1.0f, 1.0f + __expf(-x));
}
static __device__ __forceinline__ float tanh_fast(float x) {
    float e = __expf(-2.0f * fabsf(x));
    float t = __fdividef(1.0f - e, 1.0f + e);
    return copysignf(t, x);
}

// ---------------- smem layout (byte offsets in dynamic smem) ----------------
// Lo tiles only where consumed: H1L (FC 3-term). Y and H0 are hi-only now.
#define T_YH0 0
#define T_YH1 16384
#define T_H0H 32768
#define T_H1H 49152
#define T_H1L 65536
#define SM_WBUF 81920               /* 2 x 32KB stream buffers */
#define SM_B0   147456              /* 256 floats */
#define SM_B1   148480              /* 256 floats */
#define SM_BFC  149504              /* 128 floats */
#define SM_TOTAL 150016

// ---------------- per-step chunk sequence (6 chunks; all 32KB) ----------------
// 0: W0h k=y0   A=YH0
// 1: W0h k=y1   A=YH1
// 2: W0h k=h0   A=H0H         -> L0 epilogue (writes H0H)
// 3: W1h k=h0   A=H0H
// 4: W1h k=h1   A=H1H         -> L1 epilogue (writes H1H + H1L)
// 5: Wf hi+lo   A=H1H/H1L     -> FC epilogue (3-term, writes YH + gmem)
__constant__ uint32_t c_src[6] = { 0, 16384, 32768, 49152, 65536, 81920 };
__constant__ uint32_t c_ahi[6] = { T_YH0, T_YH1, T_H0H, T_H0H, T_H1H, T_H1H };

// ---------------- weight prep ----------------
__global__ void prep_kernel(const float* __restrict__ Wih0, const float* __restrict__ Whh0,
                            const float* __restrict__ Wih1, const float* __restrict__ Whh1,
                            const float* __restrict__ Wfc) {
    int i = blockIdx.x * blockDim.x + threadIdx.x;
    int stride = gridDim.x * blockDim.x;
    // L0 hi chunks (plain bf16 weights), gate-interleaved n
    for (int idx = i; idx < 3 * 16384; idx += stride) {
        int ch = idx >> 14, e = idx & 16383, n = e >> 6, kk = e & 63;
        int g = (n >> 3) & 3, u = ((n >> 5) << 3) | (n & 7);
        float w = (ch < 2) ? Wih0[(g * 64 + u) * 128 + ch * 64 + kk]
                           : Whh0[(g * 64 + u) * 64 + kk];
        uint32_t sw = SWZ128((uint32_t)n * 128u + (uint32_t)kk * 2u) >> 1;
        g_WB[ch * 16384 + sw] = __float2bfloat16(w);
    }
    // L1 hi chunks
    for (int idx = i; idx < 2 * 16384; idx += stride) {
        int ch = idx >> 14, e = idx & 16383, n = e >> 6, kk = e & 63;
        int g = (n >> 3) & 3, u = ((n >> 5) << 3) | (n & 7);
        float w = (ch == 0) ? Wih1[(g * 64 + u) * 64 + kk]
                            : Whh1[(g * 64 + u) * 64 + kk];
        uint32_t sw = SWZ128((uint32_t)n * 128u + (uint32_t)kk * 2u) >> 1;
        g_WB[49152 + ch * 16384 + sw] = __float2bfloat16(w);
    }
    // FC: hi at 81920, lo at 90112 (3-term kept for output accuracy)
    for (int idx = i; idx < 8192; idx += stride) {
        int n = idx >> 6, kk = idx & 63;
        float w = Wfc[n * 64 + kk];
        uint32_t sw = SWZ128((uint32_t)n * 128u + (uint32_t)kk * 2u) >> 1;
        __nv_bfloat16 h = __float2bfloat16(w);
        g_WB[81920 + sw] = h;
        g_WB[90112 + sw] = __float2bfloat16(w - __bfloat162float(h));
    }
}

// ---------------- activation stores ----------------
static __device__ __forceinline__ void st_hi2(char* th, uint32_t off, float a, float b) {
    uint32_t sw = SWZ128(off);
    __nv_bfloat162 hp;
    hp.x = __float2bfloat16(a);
    hp.y = __float2bfloat16(b);
    *(__nv_bfloat162*)(th + sw) = hp;
}
static __device__ __forceinline__ void st_hilo2(char* th, char* tl, uint32_t off,
                                                float a, float b) {
    uint32_t sw = SWZ128(off);
    __nv_bfloat16 ah = __float2bfloat16(a), bh = __float2bfloat16(b);
    __nv_bfloat162 hp; hp.x = ah; hp.y = bh;
    *(__nv_bfloat162*)(th + sw) = hp;
    __nv_bfloat162 lp;
    lp.x = __float2bfloat16(a - __bfloat162float(ah));
    lp.y = __float2bfloat16(b - __bfloat162float(bh));
    *(__nv_bfloat162*)(tl + sw) = lp;
}

// ---------------- main kernel ----------------
extern __shared__ char smem[];

__global__ __launch_bounds__(THREADS, 1)
void lstm_hmma_kernel(const float* __restrict__ x,
                      const float* __restrict__ b0, const float* __restrict__ b1,
                      const float* __restrict__ bfc,
                      float* __restrict__ ystack, float* __restrict__ ylast) {
    const uint32_t sbase = smem_u32(smem);
    const int tid = threadIdx.x, lane = tid & 31, w = tid >> 5;
    const int wg = w >> 3;              // warp-group: row half (0: rows 0-63, 1: 64-127)
    const int wl = w & 7;               // n-position within group
    const int row0 = blockIdx.x * 128;

    // ---- init: biases -> smem, x -> Y tiles, zero H tiles ----
    if (tid < 256) {
        ((float*)(smem + SM_B0))[tid] = b0[tid];
        ((float*)(smem + SM_B1))[tid] = b1[tid];
        if (tid < 128) ((float*)(smem + SM_BFC))[tid] = bfc[tid];
    }
    {
        uint4 z = make_uint4(0, 0, 0, 0);
        for (uint32_t i = (uint32_t)tid * 16u; i < 49152u; i += THREADS * 16u)
            *(uint4*)(smem + T_H0H + i) = z;   // zero H0H, H1H, H1L
        const float4* x4 = (const float4*)(x + (size_t)row0 * 128);
        for (int e = tid; e < 128 * 32; e += THREADS) {
            int r = e >> 5, c4 = e & 31;
            float4 v = x4[r * 32 + c4];
            int c = c4 * 4;
            char* th = (char*)smem + ((c < 64) ? T_YH0 : T_YH1);
            uint32_t off = (uint32_t)r * 128u + (uint32_t)(c & 63) * 2u;
            st_hi2(th, off, v.x, v.y);
            st_hi2(th, off + 4, v.z, v.w);
        }
    }

    // ---- per-thread roles ----
    const int l4 = lane >> 2;            // row within 8
    const int ln = lane & 3;             // n-pair selector
    const int u0 = wl * 8 + 2 * ln;      // unit pair (gates)
    const uint32_t xm = (uint32_t)(lane & 7) << 4;   // lane-constant swizzle mask
    const int arow = wg * 64 + (lane & 15);

    const float* b0s  = (const float*)(smem + SM_B0);
    const float* b1s  = (const float*)(smem + SM_B1);
    const float* bfcs = (const float*)(smem + SM_BFC);

    float c0s[16], c1s[16];
#pragma unroll
    for (int i = 0; i < 16; ++i) { c0s[i] = 0.0f; c1s[i] = 0.0f; }

    float acc[4][4][4];

    // prologue: issue chunk 0
    {
        const char* src = (const char*)(g_WB + c_src[0]);
        uint32_t dst = sbase + SM_WBUF;
        for (uint32_t off = (uint32_t)tid * 16u; off < 32768u; off += THREADS * 16u)
            cp16(dst + off, src + off);
        cp_commit();
    }

#pragma unroll 1
    for (int t = 0; t < NSTEPS; ++t) {
#pragma unroll 1
        for (int c = 0; c < 6; ++c) {
            const bool isFC = (c == 5);
            const int epi = (c == 2) ? 1 : (c == 4) ? 2 : (c == 5) ? 3 : 0;
            const bool start = (c == 0) | (c == 3) | (c == 5);

            __syncthreads();   // buffer (c+1)&1 free + activation-tile writes ordered

            // issue next chunk (wrap to next step's chunk 0)
            const bool last = (t == NSTEPS - 1) && (c == 5);
            if (!last) {
                int nc = (c + 1) % 6;
                const char* src = (const char*)(g_WB + c_src[nc]);
                uint32_t dst = sbase + SM_WBUF + (uint32_t)(~c & 1) * 32768u;
                for (uint32_t off = (uint32_t)tid * 16u; off < 32768u; off += THREADS * 16u)
                    cp16(dst + off, src + off);
                cp_commit();
                asm volatile("cp.async.wait_group 1;" ::: "memory");
            } else {
                asm volatile("cp.async.wait_group 0;" ::: "memory");
            }
            __syncthreads();   // chunk c visible to all warps

            // ---- acc init at phase start (biases from smem) ----
            if (start) {
                if (isFC) {
                    float bb[2][2];
#pragma unroll
                    for (int v = 0; v < 2; ++v)
#pragma unroll
                        for (int j = 0; j < 2; ++j)
                            bb[v][j] = bfcs[wl * 16 + v * 8 + 2 * ln + j];
#pragma unroll
                    for (int s = 0; s < 4; ++s)
#pragma unroll
                        for (int v = 0; v < 4; ++v)
#pragma unroll
                            for (int q = 0; q < 4; ++q)
                                acc[s][v][q] = (v < 2) ? bb[v][q & 1] : 0.0f;
                } else {
                    const float* bs = (c == 0) ? b0s : b1s;
                    float bb[4][2];
#pragma unroll
                    for (int v = 0; v < 4; ++v)
#pragma unroll
                        for (int j = 0; j < 2; ++j)
                            bb[v][j] = bs[v * 64 + u0 + j];
#pragma unroll
                    for (int s = 0; s < 4; ++s)
#pragma unroll
                        for (int v = 0; v < 4; ++v)
#pragma unroll
                            for (int q = 0; q < 4; ++q)
                                acc[s][v][q] = bb[v][q & 1];
                }
            }

            // ---- mma over this chunk (64 k) ----
            const uint32_t buf = sbase + SM_WBUF + (uint32_t)(c & 1) * 32768u;
            const uint32_t ahi = sbase + c_ahi[c];
            const int nb = (isFC ? wl * 16 : wl * 32) + (lane & 15);
            const uint32_t brow = buf + (uint32_t)nb * 128u;
            const uint32_t hi16 = (uint32_t)((lane >> 4) << 4);

#pragma unroll
            for (int k16 = 0; k16 < 4; ++k16) {
                const uint32_t cx = ((uint32_t)(k16 * 32) + hi16) ^ xm;
                // B fragments: gates -> 32 n rows (2 ldm); FC -> 16 hi rows + 16 lo rows
                uint32_t bfr[4][2];
                {
                    uint32_t r[4];
                    ldm_x4(r, brow + cx);
                    bfr[0][0] = r[0]; bfr[1][0] = r[1]; bfr[0][1] = r[2]; bfr[1][1] = r[3];
                    ldm_x4(r, brow + (isFC ? 16384u : 2048u) + cx);
                    bfr[2][0] = r[0]; bfr[3][0] = r[1]; bfr[2][1] = r[2]; bfr[3][1] = r[3];
                }
#pragma unroll
                for (int s = 0; s < 4; ++s) {
                    const uint32_t aoff = (uint32_t)(arow + s * 16) * 128u + cx;
                    uint32_t ah[4];
                    ldm_x4(ah, ahi + aoff);
                    if (isFC) {
                        uint32_t al[4];
                        ldm_x4(al, sbase + T_H1L + aoff);
#pragma unroll
                        for (int v = 0; v < 2; ++v) {
                            mma16816(acc[s][v], ah, bfr[v]);
                            mma16816(acc[s][v], al, bfr[v]);
                            mma16816(acc[s][v], ah, bfr[v + 2]);   // hi-A x lo-W
                        }
                    } else {
#pragma unroll
                        for (int v = 0; v < 4; ++v)
                            mma16816(acc[s][v], ah, bfr[v]);
                    }
                }
            }

            // ---- epilogues ----
            if (epi == 1 || epi == 2) {
                __syncthreads();   // all mma reads of H tile done before overwrite
                float* cst = (epi == 1) ? c0s : c1s;
                char* th = (char*)smem + ((epi == 1) ? T_H0H : T_H1H);
                char* tl = (char*)smem + T_H1L;
#pragma unroll
                for (int s = 0; s < 4; ++s)
#pragma unroll
                    for (int rh = 0; rh < 2; ++rh) {
                        float h2[2];
#pragma unroll
                        for (int j = 0; j < 2; ++j) {
                            float iv = sigm(acc[s][0][rh * 2 + j]);
                            float fv = sigm(acc[s][1][rh * 2 + j]);
                            float gv = tanh_fast(acc[s][2][rh * 2 + j]);
                            float ov = sigm(acc[s][3][rh * 2 + j]);
                            int ci = s * 4 + rh * 2 + j;
                            float cv = fv * cst[ci] + iv * gv;
                            cst[ci] = cv;
                            h2[j] = ov * tanh_fast(cv);
                        }
                        int row = wg * 64 + s * 16 + l4 + rh * 8;
                        uint32_t off = (uint32_t)row * 128u + (uint32_t)u0 * 2u;
                        if (epi == 1) st_hi2(th, off, h2[0], h2[1]);
                        else          st_hilo2(th, tl, off, h2[0], h2[1]);
                    }
            } else if (epi == 3) {
                // FC epilogue: y = acc (+bias already), write gmem + Y tiles (hi only)
                const size_t tb = (size_t)t * B_ROWS * DDIM;
#pragma unroll
                for (int s = 0; s < 4; ++s)
#pragma unroll
                    for (int rh = 0; rh < 2; ++rh) {
                        int row = wg * 64 + s * 16 + l4 + rh * 8;
                        float* ys = ystack ? (ystack + tb + (size_t)(row0 + row) * DDIM)
                                           : nullptr;
                        float* yl = (ylast && t == NSTEPS - 1)
                                        ? (ylast + (size_t)(row0 + row) * DDIM) : nullptr;
#pragma unroll
                        for (int v = 0; v < 2; ++v) {
                            int d = wl * 16 + v * 8 + 2 * ln;
                            float y0 = acc[s][v][rh * 2 + 0];
                            float y1 = acc[s][v][rh * 2 + 1];
                            if (ys) { float2 p = make_float2(y0, y1); *(float2*)(ys + d) = p; }
                            if (yl) { float2 p = make_float2(y0, y1); *(float2*)(yl + d) = p; }
                            char* th = (char*)smem + ((d < 64) ? T_YH0 : T_YH1);
                            st_hi2(th, (uint32_t)row * 128u + (uint32_t)(d & 63) * 2u,
                                   y0, y1);
                        }
                    }
            }
        }
    }
}

extern "C" void kernel_launch(void* const* d_in, const int* in_sizes, int n_in,
                              void* d_out, int out_size) {
    const float* x    = (const float*)d_in[0];
    const float* Wih0 = (const float*)d_in[1];
    const float* Whh0 = (const float*)d_in[2];
    const float* b0   = (const float*)d_in[3];
    const float* Wih1 = (const float*)d_in[4];
    const float* Whh1 = (const float*)d_in[5];
    const float* b1   = (const float*)d_in[6];
    const float* Wfc  = (const float*)d_in[7];
    const float* bfc  = (const float*)d_in[8];
    (void)in_sizes; (void)n_in;

    float* out = (float*)d_out;
    const long long BD = (long long)B_ROWS * DDIM;
    float* ylast  = nullptr;
    float* ystack = nullptr;
    if ((long long)out_size >= BD * (NSTEPS + 1)) {
        ylast  = out;
        ystack = out + BD;
    } else if ((long long)out_size >= BD * NSTEPS) {
        ystack = out;
    } else {
        ylast = out;
    }

    cudaFuncSetAttribute(lstm_hmma_kernel,
                         cudaFuncAttributeMaxDynamicSharedMemorySize, SM_TOTAL);

    prep_kernel<<<64, 256>>>(Wih0, Whh0, Wih1, Whh1, Wfc);
    lstm_hmma_kernel<<<B_ROWS / 128, THREADS, SM_TOTAL>>>(x, b0, b1, bfc, ystack, ylast);
}

// round 13
// speedup vs baseline: 4.8432x; 1.0790x over previous
#include <cuda_runtime.h>
#include <cuda_bf16.h>
#include <cstdint>
#include <cstddef>

#define B_ROWS 32768
#define DDIM   128
#define NSTEPS 32
#define THREADS 256
#define M_TILE 64

// ---------------- packed weight scratch ----------------
// [W0h 49152][W1h 32768][Wfh 8192][Wfl 8192] bf16 elems (+ slack).
// Each 16384-elem chunk = [256 n x 64 k], 128B rows, SW128 swizzled.
// Gate chunks use unit-interleaved n: n = (u>>3)*32 + g*8 + (u&7).
// FC hi at 81920, FC lo at 90112 (contiguous 32KB pair).
__device__ __align__(128) __nv_bfloat16 g_WB[98304];

#define SWZ128(o) ((o) ^ (((o) >> 3) & 0x70))

static __device__ __forceinline__ uint32_t smem_u32(const void* p) {
    uint32_t a;
    asm("{ .reg .u64 t; cvta.to.shared.u64 t, %1; cvt.u32.u64 %0, t; }" : "=r"(a) : "l"(p));
    return a;
}

// ---------------- mma / ldmatrix / cp.async ----------------
static __device__ __forceinline__ void ldm_x4(uint32_t* r, uint32_t addr) {
    asm volatile("ldmatrix.sync.aligned.m8n8.x4.shared.b16 {%0,%1,%2,%3}, [%4];"
                 : "=r"(r[0]), "=r"(r[1]), "=r"(r[2]), "=r"(r[3]) : "r"(addr));
}
static __device__ __forceinline__ void mma16816(float* c, const uint32_t* a, const uint32_t* b) {
    asm volatile(
        "mma.sync.aligned.m16n8k16.row.col.f32.bf16.bf16.f32 "
        "{%0,%1,%2,%3}, {%4,%5,%6,%7}, {%8,%9}, {%0,%1,%2,%3};"
        : "+f"(c[0]), "+f"(c[1]), "+f"(c[2]), "+f"(c[3])
        : "r"(a[0]), "r"(a[1]), "r"(a[2]), "r"(a[3]), "r"(b[0]), "r"(b[1]));
}
static __device__ __forceinline__ void cp16(uint32_t dst, const void* src) {
    asm volatile("cp.async.cg.shared.global [%0], [%1], 16;" :: "r"(dst), "l"(src));
}
static __device__ __forceinline__ void cp_commit() {
    asm volatile("cp.async.commit_group;" ::: "memory");
}

static __device__ __forceinline__ float sigm(float x) {
    return __fdividef(1.0f, 1.0f + __expf(-x));
}
static __device__ __forceinline__ float tanh_fast(float x) {
    float e = __expf(-2.0f * fabsf(x));
    float t = __fdividef(1.0f - e, 1.0f + e);
    return copysignf(t, x);
}

// ---------------- smem layout (byte offsets in dynamic smem) ----------------
// M=64 rows -> 8KB activation tiles. Lo tile only for H1 (FC 3-term).
#define T_YH0 0
#define T_YH1 8192
#define T_H0H 16384
#define T_H1H 24576
#define T_H1L 32768
#define SM_WBUF 40960               /* 2 x 32KB stream buffers */
#define SM_B0   106496              /* 256 floats */
#define SM_B1   107520              /* 256 floats */
#define SM_BFC  108544              /* 128 floats */
#define SM_TOTAL 109056             /* 2 CTAs/SM: 218112 <= 227KB */

// ---------------- per-step chunk sequence (6 chunks; all 32KB) ----------------
// 0: W0h k=y0   A=YH0
// 1: W0h k=y1   A=YH1
// 2: W0h k=h0   A=H0H         -> L0 epilogue (writes H0H)
// 3: W1h k=h0   A=H0H
// 4: W1h k=h1   A=H1H         -> L1 epilogue (writes H1H + H1L)
// 5: Wf hi+lo   A=H1H/H1L     -> FC epilogue (3-term, writes YH + gmem)
__constant__ uint32_t c_src[6] = { 0, 16384, 32768, 49152, 65536, 81920 };
__constant__ uint32_t c_ahi[6] = { T_YH0, T_YH1, T_H0H, T_H0H, T_H1H, T_H1H };

// ---------------- weight prep ----------------
__global__ void prep_kernel(const float* __restrict__ Wih0, const float* __restrict__ Whh0,
                            const float* __restrict__ Wih1, const float* __restrict__ Whh1,
                            const float* __restrict__ Wfc) {
    int i = blockIdx.x * blockDim.x + threadIdx.x;
    int stride = gridDim.x * blockDim.x;
    // L0 hi chunks (plain bf16 weights), gate-interleaved n
    for (int idx = i; idx < 3 * 16384; idx += stride) {
        int ch = idx >> 14, e = idx & 16383, n = e >> 6, kk = e & 63;
        int g = (n >> 3) & 3, u = ((n >> 5) << 3) | (n & 7);
        float w = (ch < 2) ? Wih0[(g * 64 + u) * 128 + ch * 64 + kk]
                           : Whh0[(g * 64 + u) * 64 + kk];
        uint32_t sw = SWZ128((uint32_t)n * 128u + (uint32_t)kk * 2u) >> 1;
        g_WB[ch * 16384 + sw] = __float2bfloat16(w);
    }
    // L1 hi chunks
    for (int idx = i; idx < 2 * 16384; idx += stride) {
        int ch = idx >> 14, e = idx & 16383, n = e >> 6, kk = e & 63;
        int g = (n >> 3) & 3, u = ((n >> 5) << 3) | (n & 7);
        float w = (ch == 0) ? Wih1[(g * 64 + u) * 64 + kk]
                            : Whh1[(g * 64 + u) * 64 + kk];
        uint32_t sw = SWZ128((uint32_t)n * 128u + (uint32_t)kk * 2u) >> 1;
        g_WB[49152 + ch * 16384 + sw] = __float2bfloat16(w);
    }
    // FC: hi at 81920, lo at 90112 (3-term kept for output accuracy)
    for (int idx = i; idx < 8192; idx += stride) {
        int n = idx >> 6, kk = idx & 63;
        float w = Wfc[n * 64 + kk];
        uint32_t sw = SWZ128((uint32_t)n * 128u + (uint32_t)kk * 2u) >> 1;
        __nv_bfloat16 h = __float2bfloat16(w);
        g_WB[81920 + sw] = h;
        g_WB[90112 + sw] = __float2bfloat16(w - __bfloat162float(h));
    }
}

// ---------------- activation stores ----------------
static __device__ __forceinline__ void st_hi2(char* th, uint32_t off, float a, float b) {
    uint32_t sw = SWZ128(off);
    __nv_bfloat162 hp;
    hp.x = __float2bfloat16(a);
    hp.y = __float2bfloat16(b);
    *(__nv_bfloat162*)(th + sw) = hp;
}
static __device__ __forceinline__ void st_hilo2(char* th, char* tl, uint32_t off,
                                                float a, float b) {
    uint32_t sw = SWZ128(off);
    __nv_bfloat16 ah = __float2bfloat16(a), bh = __float2bfloat16(b);
    __nv_bfloat162 hp; hp.x = ah; hp.y = bh;
    *(__nv_bfloat162*)(th + sw) = hp;
    __nv_bfloat162 lp;
    lp.x = __float2bfloat16(a - __bfloat162float(ah));
    lp.y = __float2bfloat16(b - __bfloat162float(bh));
    *(__nv_bfloat162*)(tl + sw) = lp;
}

// ---------------- main kernel ----------------
extern __shared__ char smem[];

__global__ __launch_bounds__(THREADS, 2)
void lstm_hmma_kernel(const float* __restrict__ x,
                      const float* __restrict__ b0, const float* __restrict__ b1,
                      const float* __restrict__ bfc,
                      float* __restrict__ ystack, float* __restrict__ ylast) {
    const uint32_t sbase = smem_u32(smem);
    const int tid = threadIdx.x, lane = tid & 31, w = tid >> 5;   // w = n-position (0..7)
    const int row0 = blockIdx.x * M_TILE;

    // ---- init: biases -> smem, x -> Y tiles, zero H tiles ----
    ((float*)(smem + SM_B0))[tid] = b0[tid];
    ((float*)(smem + SM_B1))[tid] = b1[tid];
    if (tid < 128) ((float*)(smem + SM_BFC))[tid] = bfc[tid];
    {
        uint4 z = make_uint4(0, 0, 0, 0);
        for (uint32_t i = (uint32_t)tid * 16u; i < 24576u; i += THREADS * 16u)
            *(uint4*)(smem + T_H0H + i) = z;   // zero H0H, H1H, H1L
        const float4* x4 = (const float4*)(x + (size_t)row0 * 128);
        for (int e = tid; e < M_TILE * 32; e += THREADS) {
            int r = e >> 5, c4 = e & 31;
            float4 v = x4[r * 32 + c4];
            int c = c4 * 4;
            char* th = (char*)smem + ((c < 64) ? T_YH0 : T_YH1);
            uint32_t off = (uint32_t)r * 128u + (uint32_t)(c & 63) * 2u;
            st_hi2(th, off, v.x, v.y);
            st_hi2(th, off + 4, v.z, v.w);
        }
    }

    // ---- per-thread roles ----
    const int l4 = lane >> 2;            // row within 8
    const int ln = lane & 3;             // n-pair selector
    const int u0 = w * 8 + 2 * ln;       // unit pair (gates)
    const uint32_t xm = (uint32_t)(lane & 7) << 4;   // lane-constant swizzle mask
    const int arow = lane & 15;

    const float* b0s  = (const float*)(smem + SM_B0);
    const float* b1s  = (const float*)(smem + SM_B1);
    const float* bfcs = (const float*)(smem + SM_BFC);

    float c0s[16], c1s[16];
#pragma unroll
    for (int i = 0; i < 16; ++i) { c0s[i] = 0.0f; c1s[i] = 0.0f; }

    float acc[4][4][4];

    // prologue: issue chunk 0
    {
        const char* src = (const char*)(g_WB + c_src[0]);
        uint32_t dst = sbase + SM_WBUF;
        for (uint32_t off = (uint32_t)tid * 16u; off < 32768u; off += THREADS * 16u)
            cp16(dst + off, src + off);
        cp_commit();
    }

#pragma unroll 1
    for (int t = 0; t < NSTEPS; ++t) {
#pragma unroll 1
        for (int c = 0; c < 6; ++c) {
            const bool isFC = (c == 5);
            const int epi = (c == 2) ? 1 : (c == 4) ? 2 : (c == 5) ? 3 : 0;
            const bool start = (c == 0) | (c == 3) | (c == 5);

            __syncthreads();   // buffer (c+1)&1 free + activation-tile writes ordered

            // issue next chunk (wrap to next step's chunk 0)
            const bool last = (t == NSTEPS - 1) && (c == 5);
            if (!last) {
                int nc = (c + 1) % 6;
                const char* src = (const char*)(g_WB + c_src[nc]);
                uint32_t dst = sbase + SM_WBUF + (uint32_t)(~c & 1) * 32768u;
                for (uint32_t off = (uint32_t)tid * 16u; off < 32768u; off += THREADS * 16u)
                    cp16(dst + off, src + off);
                cp_commit();
                asm volatile("cp.async.wait_group 1;" ::: "memory");
            } else {
                asm volatile("cp.async.wait_group 0;" ::: "memory");
            }
            __syncthreads();   // chunk c visible to all warps

            // ---- acc init at phase start (biases from smem) ----
            if (start) {
                if (isFC) {
                    float bb[2][2];
#pragma unroll
                    for (int v = 0; v < 2; ++v)
#pragma unroll
                        for (int j = 0; j < 2; ++j)
                            bb[v][j] = bfcs[w * 16 + v * 8 + 2 * ln + j];
#pragma unroll
                    for (int s = 0; s < 4; ++s)
#pragma unroll
                        for (int v = 0; v < 4; ++v)
#pragma unroll
                            for (int q = 0; q < 4; ++q)
                                acc[s][v][q] = (v < 2) ? bb[v][q & 1] : 0.0f;
                } else {
                    const float* bs = (c == 0) ? b0s : b1s;
                    float bb[4][2];
#pragma unroll
                    for (int v = 0; v < 4; ++v)
#pragma unroll
                        for (int j = 0; j < 2; ++j)
                            bb[v][j] = bs[v * 64 + u0 + j];
#pragma unroll
                    for (int s = 0; s < 4; ++s)
#pragma unroll
                        for (int v = 0; v < 4; ++v)
#pragma unroll
                            for (int q = 0; q < 4; ++q)
                                acc[s][v][q] = bb[v][q & 1];
                }
            }

            // ---- mma over this chunk (64 k) ----
            const uint32_t buf = sbase + SM_WBUF + (uint32_t)(c & 1) * 32768u;
            const uint32_t ahi = sbase + c_ahi[c];
            const int nb = (isFC ? w * 16 : w * 32) + (lane & 15);
            const uint32_t brow = buf + (uint32_t)nb * 128u;
            const uint32_t hi16 = (uint32_t)((lane >> 4) << 4);

#pragma unroll
            for (int k16 = 0; k16 < 4; ++k16) {
                const uint32_t cx = ((uint32_t)(k16 * 32) + hi16) ^ xm;
                // B fragments: gates -> 32 n rows (2 ldm); FC -> 16 hi rows + 16 lo rows
                uint32_t bfr[4][2];
                {
                    uint32_t r[4];
                    ldm_x4(r, brow + cx);
                    bfr[0][0] = r[0]; bfr[1][0] = r[1]; bfr[0][1] = r[2]; bfr[1][1] = r[3];
                    ldm_x4(r, brow + (isFC ? 16384u : 2048u) + cx);
                    bfr[2][0] = r[0]; bfr[3][0] = r[1]; bfr[2][1] = r[2]; bfr[3][1] = r[3];
                }
#pragma unroll
                for (int s = 0; s < 4; ++s) {
                    const uint32_t aoff = (uint32_t)(arow + s * 16) * 128u + cx;
                    uint32_t ah[4];
                    ldm_x4(ah, ahi + aoff);
                    if (isFC) {
                        uint32_t al[4];
                        ldm_x4(al, sbase + T_H1L + aoff);
#pragma unroll
                        for (int v = 0; v < 2; ++v) {
                            mma16816(acc[s][v], ah, bfr[v]);
                            mma16816(acc[s][v], al, bfr[v]);
                            mma16816(acc[s][v], ah, bfr[v + 2]);   // hi-A x lo-W
                        }
                    } else {
#pragma unroll
                        for (int v = 0; v < 4; ++v)
                            mma16816(acc[s][v], ah, bfr[v]);
                    }
                }
            }

            // ---- epilogues ----
            if (epi == 1 || epi == 2) {
                __syncthreads();   // all mma reads of H tile done before overwrite
                float* cst = (epi == 1) ? c0s : c1s;
                char* th = (char*)smem + ((epi == 1) ? T_H0H : T_H1H);
                char* tl = (char*)smem + T_H1L;
#pragma unroll
                for (int s = 0; s < 4; ++s)
#pragma unroll
                    for (int rh = 0; rh < 2; ++rh) {
                        float h2[2];
#pragma unroll
                        for (int j = 0; j < 2; ++j) {
                            float iv = sigm(acc[s][0][rh * 2 + j]);
                            float fv = sigm(acc[s][1][rh * 2 + j]);
                            float gv = tanh_fast(acc[s][2][rh * 2 + j]);
                            float ov = sigm(acc[s][3][rh * 2 + j]);
                            int ci = s * 4 + rh * 2 + j;
                            float cv = fv * cst[ci] + iv * gv;
                            cst[ci] = cv;
                            h2[j] = ov * tanh_fast(cv);
                        }
                        int row = s * 16 + l4 + rh * 8;
                        uint32_t off = (uint32_t)row * 128u + (uint32_t)u0 * 2u;
                        if (epi == 1) st_hi2(th, off, h2[0], h2[1]);
                        else          st_hilo2(th, tl, off, h2[0], h2[1]);
                    }
            } else if (epi == 3) {
                // FC epilogue: y = acc (+bias already), write gmem + Y tiles (hi only)
                const size_t tb = (size_t)t * B_ROWS * DDIM;
#pragma unroll
                for (int s = 0; s < 4; ++s)
#pragma unroll
                    for (int rh = 0; rh < 2; ++rh) {
                        int row = s * 16 + l4 + rh * 8;
                        float* ys = ystack ? (ystack + tb + (size_t)(row0 + row) * DDIM)
                                           : nullptr;
                        float* yl = (ylast && t == NSTEPS - 1)
                                        ? (ylast + (size_t)(row0 + row) * DDIM) : nullptr;
#pragma unroll
                        for (int v = 0; v < 2; ++v) {
                            int d = w * 16 + v * 8 + 2 * ln;
                            float y0 = acc[s][v][rh * 2 + 0];
                            float y1 = acc[s][v][rh * 2 + 1];
                            if (ys) { float2 p = make_float2(y0, y1); *(float2*)(ys + d) = p; }
                            if (yl) { float2 p = make_float2(y0, y1); *(float2*)(yl + d) = p; }
                            char* th = (char*)smem + ((d < 64) ? T_YH0 : T_YH1);
                            st_hi2(th, (uint32_t)row * 128u + (uint32_t)(d & 63) * 2u,
                                   y0, y1);
                        }
                    }
            }
        }
    }
}

extern "C" void kernel_launch(void* const* d_in, const int* in_sizes, int n_in,
                              void* d_out, int out_size) {
    const float* x    = (const float*)d_in[0];
    const float* Wih0 = (const float*)d_in[1];
    const float* Whh0 = (const float*)d_in[2];
    const float* b0   = (const float*)d_in[3];
    const float* Wih1 = (const float*)d_in[4];
    const float* Whh1 = (const float*)d_in[5];
    const float* b1   = (const float*)d_in[6];
    const float* Wfc  = (const float*)d_in[7];
    const float* bfc  = (const float*)d_in[8];
    (void)in_sizes; (void)n_in;

    float* out = (float*)d_out;
    const long long BD = (long long)B_ROWS * DDIM;
    float* ylast  = nullptr;
    float* ystack = nullptr;
    if ((long long)out_size >= BD * (NSTEPS + 1)) {
        ylast  = out;
        ystack = out + BD;
    } else if ((long long)out_size >= BD * NSTEPS) {
        ystack = out;
    } else {
        ylast = out;
    }

    cudaFuncSetAttribute(lstm_hmma_kernel,
                         cudaFuncAttributeMaxDynamicSharedMemorySize, SM_TOTAL);

    prep_kernel<<<64, 256>>>(Wih0, Whh0, Wih1, Whh1, Wfc);
    lstm_hmma_kernel<<<B_ROWS / M_TILE, THREADS, SM_TOTAL>>>(x, b0, b1, bfc, ystack, ylast);
}

// round 15
// speedup vs baseline: 5.4345x; 1.1221x over previous
#include <cuda_runtime.h>
#include <cuda_bf16.h>
#include <cstdint>
#include <cstddef>

#define B_ROWS 32768
#define DDIM   128
#define NSTEPS 32
#define THREADS 256
#define M_TILE 64

// ---------------- packed weight scratch ----------------
// [W0h 49152][W1h 32768][Wfh 8192][Wfl 8192] bf16 elems (+ slack).
// Each 16384-elem chunk = [256 n x 64 k], 128B rows, SW128 swizzled.
// Gate chunks use unit-interleaved n: n = (u>>3)*32 + g*8 + (u&7).
// FC hi at 81920, FC lo at 90112 (contiguous 32KB pair).
__device__ __align__(128) __nv_bfloat16 g_WB[98304];

#define SWZ128(o) ((o) ^ (((o) >> 3) & 0x70))

static __device__ __forceinline__ uint32_t smem_u32(const void* p) {
    uint32_t a;
    asm("{ .reg .u64 t; cvta.to.shared.u64 t, %1; cvt.u32.u64 %0, t; }" : "=r"(a) : "l"(p));
    return a;
}

// ---------------- mma / ldmatrix / cp.async ----------------
static __device__ __forceinline__ void ldm_x4(uint32_t* r, uint32_t addr) {
    asm volatile("ldmatrix.sync.aligned.m8n8.x4.shared.b16 {%0,%1,%2,%3}, [%4];"
                 : "=r"(r[0]), "=r"(r[1]), "=r"(r[2]), "=r"(r[3]) : "r"(addr));
}
static __device__ __forceinline__ void mma16816(float* c, const uint32_t* a, const uint32_t* b) {
    asm volatile(
        "mma.sync.aligned.m16n8k16.row.col.f32.bf16.bf16.f32 "
        "{%0,%1,%2,%3}, {%4,%5,%6,%7}, {%8,%9}, {%0,%1,%2,%3};"
        : "+f"(c[0]), "+f"(c[1]), "+f"(c[2]), "+f"(c[3])
        : "r"(a[0]), "r"(a[1]), "r"(a[2]), "r"(a[3]), "r"(b[0]), "r"(b[1]));
}
static __device__ __forceinline__ void cp16(uint32_t dst, const void* src) {
    asm volatile("cp.async.cg.shared.global [%0], [%1], 16;" :: "r"(dst), "l"(src));
}
static __device__ __forceinline__ void cp_commit() {
    asm volatile("cp.async.commit_group;" ::: "memory");
}

// ---------------- fast activation math (MUFU.TANH) ----------------
static __device__ __forceinline__ float tanh_m(float x) {
    float r;
    asm("tanh.approx.f32 %0, %1;" : "=f"(r) : "f"(x));
    return r;
}
static __device__ __forceinline__ float sigm(float x) {
    return fmaf(0.5f, tanh_m(0.5f * x), 0.5f);
}

// ---------------- smem layout (byte offsets in dynamic smem) ----------------
// M=64 rows -> 8KB activation tiles. Lo tile only for H1 (FC 3-term).
#define T_YH0 0
#define T_YH1 8192
#define T_H0H 16384
#define T_H1H 24576
#define T_H1L 32768
#define SM_WBUF 40960               /* 2 x 32KB stream buffers */
#define SM_B0   106496              /* 256 floats */
#define SM_B1   107520              /* 256 floats */
#define SM_BFC  108544              /* 128 floats */
#define SM_TOTAL 109056             /* 2 CTAs/SM */

// ---------------- per-step chunk sequence (6 chunks; all 32KB) ----------------
// 0: W0h k=y0   A=YH0
// 1: W0h k=y1   A=YH1
// 2: W0h k=h0   A=H0H         -> L0 epilogue (writes H0H)
// 3: W1h k=h0   A=H0H
// 4: W1h k=h1   A=H1H         -> L1 epilogue (writes H1H + H1L)
// 5: Wf hi+lo   A=H1H/H1L     -> FC epilogue (3-term, writes YH + gmem)
__constant__ uint32_t c_src[6] = { 0, 16384, 32768, 49152, 65536, 81920 };
__constant__ uint32_t c_ahi[6] = { T_YH0, T_YH1, T_H0H, T_H0H, T_H1H, T_H1H };

// ---------------- weight prep ----------------
__global__ void prep_kernel(const float* __restrict__ Wih0, const float* __restrict__ Whh0,
                            const float* __restrict__ Wih1, const float* __restrict__ Whh1,
                            const float* __restrict__ Wfc) {
    int i = blockIdx.x * blockDim.x + threadIdx.x;
    int stride = gridDim.x * blockDim.x;
    // L0 hi chunks (plain bf16 weights), gate-interleaved n
    for (int idx = i; idx < 3 * 16384; idx += stride) {
        int ch = idx >> 14, e = idx & 16383, n = e >> 6, kk = e & 63;
        int g = (n >> 3) & 3, u = ((n >> 5) << 3) | (n & 7);
        float w = (ch < 2) ? Wih0[(g * 64 + u) * 128 + ch * 64 + kk]
                           : Whh0[(g * 64 + u) * 64 + kk];
        uint32_t sw = SWZ128((uint32_t)n * 128u + (uint32_t)kk * 2u) >> 1;
        g_WB[ch * 16384 + sw] = __float2bfloat16(w);
    }
    // L1 hi chunks
    for (int idx = i; idx < 2 * 16384; idx += stride) {
        int ch = idx >> 14, e = idx & 16383, n = e >> 6, kk = e & 63;
        int g = (n >> 3) & 3, u = ((n >> 5) << 3) | (n & 7);
        float w = (ch == 0) ? Wih1[(g * 64 + u) * 64 + kk]
                            : Whh1[(g * 64 + u) * 64 + kk];
        uint32_t sw = SWZ128((uint32_t)n * 128u + (uint32_t)kk * 2u) >> 1;
        g_WB[49152 + ch * 16384 + sw] = __float2bfloat16(w);
    }
    // FC: hi at 81920, lo at 90112 (3-term kept for output accuracy)
    for (int idx = i; idx < 8192; idx += stride) {
        int n = idx >> 6, kk = idx & 63;
        float w = Wfc[n * 64 + kk];
        uint32_t sw = SWZ128((uint32_t)n * 128u + (uint32_t)kk * 2u) >> 1;
        __nv_bfloat16 h = __float2bfloat16(w);
        g_WB[81920 + sw] = h;
        g_WB[90112 + sw] = __float2bfloat16(w - __bfloat162float(h));
    }
}

// ---------------- activation stores ----------------
static __device__ __forceinline__ void st_hi2(char* th, uint32_t off, float a, float b) {
    uint32_t sw = SWZ128(off);
    __nv_bfloat162 hp;
    hp.x = __float2bfloat16(a);
    hp.y = __float2bfloat16(b);
    *(__nv_bfloat162*)(th + sw) = hp;
}
static __device__ __forceinline__ void st_hilo2(char* th, char* tl, uint32_t off,
                                                float a, float b) {
    uint32_t sw = SWZ128(off);
    __nv_bfloat16 ah = __float2bfloat16(a), bh = __float2bfloat16(b);
    __nv_bfloat162 hp; hp.x = ah; hp.y = bh;
    *(__nv_bfloat162*)(th + sw) = hp;
    __nv_bfloat162 lp;
    lp.x = __float2bfloat16(a - __bfloat162float(ah));
    lp.y = __float2bfloat16(b - __bfloat162float(bh));
    *(__nv_bfloat162*)(tl + sw) = lp;
}

// ---------------- main kernel ----------------
extern __shared__ char smem[];

__global__ __launch_bounds__(THREADS, 2)
void lstm_hmma_kernel(const float* __restrict__ x,
                      const float* __restrict__ b0, const float* __restrict__ b1,
                      const float* __restrict__ bfc,
                      float* __restrict__ ystack, float* __restrict__ ylast) {
    const uint32_t sbase = smem_u32(smem);
    const int tid = threadIdx.x, lane = tid & 31, w = tid >> 5;   // w = n-position (0..7)
    const int row0 = blockIdx.x * M_TILE;

    // ---- init: biases -> smem, x -> Y tiles, zero H tiles ----
    ((float*)(smem + SM_B0))[tid] = b0[tid];
    ((float*)(smem + SM_B1))[tid] = b1[tid];
    if (tid < 128) ((float*)(smem + SM_BFC))[tid] = bfc[tid];
    {
        uint4 z = make_uint4(0, 0, 0, 0);
        for (uint32_t i = (uint32_t)tid * 16u; i < 24576u; i += THREADS * 16u)
            *(uint4*)(smem + T_H0H + i) = z;   // zero H0H, H1H, H1L
        const float4* x4 = (const float4*)(x + (size_t)row0 * 128);
        for (int e = tid; e < M_TILE * 32; e += THREADS) {
            int r = e >> 5, c4 = e & 31;
            float4 v = x4[r * 32 + c4];
            int c = c4 * 4;
            char* th = (char*)smem + ((c < 64) ? T_YH0 : T_YH1);
            uint32_t off = (uint32_t)r * 128u + (uint32_t)(c & 63) * 2u;
            st_hi2(th, off, v.x, v.y);
            st_hi2(th, off + 4, v.z, v.w);
        }
    }

    // ---- per-thread roles ----
    const int l4 = lane >> 2;            // row within 8
    const int ln = lane & 3;             // n-pair selector
    const int u0 = w * 8 + 2 * ln;       // unit pair (gates)
    const uint32_t xm = (uint32_t)(lane & 7) << 4;   // lane-constant swizzle mask
    const int arow = lane & 15;
    const uint32_t hi16 = (uint32_t)((lane >> 4) << 4);
    uint32_t cxk[4];
#pragma unroll
    for (int k = 0; k < 4; ++k) cxk[k] = ((uint32_t)(k * 32) + hi16) ^ xm;

    const float* b0s  = (const float*)(smem + SM_B0);
    const float* b1s  = (const float*)(smem + SM_B1);
    const float* bfcs = (const float*)(smem + SM_BFC);

    float c0s[16], c1s[16];
#pragma unroll
    for (int i = 0; i < 16; ++i) { c0s[i] = 0.0f; c1s[i] = 0.0f; }

    float acc[4][4][4];

    // prologue: issue chunk 0
    {
        const char* src = (const char*)(g_WB + c_src[0]);
        uint32_t dst = sbase + SM_WBUF;
        for (uint32_t off = (uint32_t)tid * 16u; off < 32768u; off += THREADS * 16u)
            cp16(dst + off, src + off);
        cp_commit();
    }

#pragma unroll 1
    for (int t = 0; t < NSTEPS; ++t) {
#pragma unroll 1
        for (int c = 0; c < 6; ++c) {
            const bool isFC = (c == 5);
            const int epi = (c == 2) ? 1 : (c == 4) ? 2 : (c == 5) ? 3 : 0;
            const bool start = (c == 0) | (c == 3) | (c == 5);

            // chunk c arrived (this thread's cp groups drained)
            asm volatile("cp.async.wait_group 0;" ::: "memory");
            // one barrier: chunk-c writes visible to all; all warps done with
            // chunk c-1 mma (buffer (c+1)&1 free); prior epilogue stores visible
            __syncthreads();

            // issue next chunk into the freed buffer
            const bool last = (t == NSTEPS - 1) && (c == 5);
            if (!last) {
                int nc = (c + 1) % 6;
                const char* src = (const char*)(g_WB + c_src[nc]);
                uint32_t dst = sbase + SM_WBUF + (uint32_t)(~c & 1) * 32768u;
                for (uint32_t off = (uint32_t)tid * 16u; off < 32768u; off += THREADS * 16u)
                    cp16(dst + off, src + off);
                cp_commit();
            }

            // ---- acc init at phase start (biases from smem) ----
            if (start) {
                if (isFC) {
                    float bb[2][2];
#pragma unroll
                    for (int v = 0; v < 2; ++v)
#pragma unroll
                        for (int j = 0; j < 2; ++j)
                            bb[v][j] = bfcs[w * 16 + v * 8 + 2 * ln + j];
#pragma unroll
                    for (int s = 0; s < 4; ++s)
#pragma unroll
                        for (int v = 0; v < 4; ++v)
#pragma unroll
                            for (int q = 0; q < 4; ++q)
                                acc[s][v][q] = (v < 2) ? bb[v][q & 1] : 0.0f;
                } else {
                    const float* bs = (c == 0) ? b0s : b1s;
                    float bb[4][2];
#pragma unroll
                    for (int v = 0; v < 4; ++v)
#pragma unroll
                        for (int j = 0; j < 2; ++j)
                            bb[v][j] = bs[v * 64 + u0 + j];
#pragma unroll
                    for (int s = 0; s < 4; ++s)
#pragma unroll
                        for (int v = 0; v < 4; ++v)
#pragma unroll
                            for (int q = 0; q < 4; ++q)
                                acc[s][v][q] = bb[v][q & 1];
                }
            }

            // ---- mma over this chunk (64 k) ----
            const uint32_t buf = sbase + SM_WBUF + (uint32_t)(c & 1) * 32768u;
            const uint32_t ahi = sbase + c_ahi[c];
            const int nb = (isFC ? w * 16 : w * 32) + (lane & 15);
            const uint32_t brow = buf + (uint32_t)nb * 128u;
            const uint32_t abase = ahi + (uint32_t)arow * 128u;

#pragma unroll
            for (int k16 = 0; k16 < 4; ++k16) {
                const uint32_t cx = cxk[k16];
                // B fragments: gates -> 32 n rows (2 ldm); FC -> 16 hi rows + 16 lo rows
                uint32_t bfr[4][2];
                {
                    uint32_t r[4];
                    ldm_x4(r, brow + cx);
                    bfr[0][0] = r[0]; bfr[1][0] = r[1]; bfr[0][1] = r[2]; bfr[1][1] = r[3];
                    ldm_x4(r, brow + (isFC ? 16384u : 2048u) + cx);
                    bfr[2][0] = r[0]; bfr[3][0] = r[1]; bfr[2][1] = r[2]; bfr[3][1] = r[3];
                }
#pragma unroll
                for (int s = 0; s < 4; ++s) {
                    const uint32_t aoff = abase + (uint32_t)(s * 2048) + cx;
                    uint32_t ah[4];
                    ldm_x4(ah, aoff);
                    if (isFC) {
                        uint32_t al[4];
                        ldm_x4(al, aoff + (T_H1L - T_H1H));
#pragma unroll
                        for (int v = 0; v < 2; ++v) {
                            mma16816(acc[s][v], ah, bfr[v]);
                            mma16816(acc[s][v], al, bfr[v]);
                            mma16816(acc[s][v], ah, bfr[v + 2]);   // hi-A x lo-W
                        }
                    } else {
#pragma unroll
                        for (int v = 0; v < 4; ++v)
                            mma16816(acc[s][v], ah, bfr[v]);
                    }
                }
            }

            // ---- epilogues ----
            if (epi == 1 || epi == 2) {
                __syncthreads();   // all mma reads of H tile done before overwrite
                float* cst = (epi == 1) ? c0s : c1s;
                char* th = (char*)smem + ((epi == 1) ? T_H0H : T_H1H);
                char* tl = (char*)smem + T_H1L;
#pragma unroll
                for (int s = 0; s < 4; ++s)
#pragma unroll
                    for (int rh = 0; rh < 2; ++rh) {
                        float h2[2];
#pragma unroll
                        for (int j = 0; j < 2; ++j) {
                            float iv = sigm(acc[s][0][rh * 2 + j]);
                            float fv = sigm(acc[s][1][rh * 2 + j]);
                            float gv = tanh_m(acc[s][2][rh * 2 + j]);
                            float ov = sigm(acc[s][3][rh * 2 + j]);
                            int ci = s * 4 + rh * 2 + j;
                            float cv = fmaf(fv, cst[ci], iv * gv);
                            cst[ci] = cv;
                            h2[j] = ov * tanh_m(cv);
                        }
                        int row = s * 16 + l4 + rh * 8;
                        uint32_t off = (uint32_t)row * 128u + (uint32_t)u0 * 2u;
                        if (epi == 1) st_hi2(th, off, h2[0], h2[1]);
                        else          st_hilo2(th, tl, off, h2[0], h2[1]);
                    }
            } else if (epi == 3) {
                // FC epilogue: y = acc (+bias already), write gmem + Y tiles (hi only)
                const size_t tb = (size_t)t * B_ROWS * DDIM;
#pragma unroll
                for (int s = 0; s < 4; ++s)
#pragma unroll
                    for (int rh = 0; rh < 2; ++rh) {
                        int row = s * 16 + l4 + rh * 8;
                        float* ys = ystack ? (ystack + tb + (size_t)(row0 + row) * DDIM)
                                           : nullptr;
                        float* yl = (ylast && t == NSTEPS - 1)
                                        ? (ylast + (size_t)(row0 + row) * DDIM) : nullptr;
#pragma unroll
                        for (int v = 0; v < 2; ++v) {
                            int d = w * 16 + v * 8 + 2 * ln;
                            float y0 = acc[s][v][rh * 2 + 0];
                            float y1 = acc[s][v][rh * 2 + 1];
                            if (ys) { float2 p = make_float2(y0, y1); *(float2*)(ys + d) = p; }
                            if (yl) { float2 p = make_float2(y0, y1); *(float2*)(yl + d) = p; }
                            char* th = (char*)smem + ((d < 64) ? T_YH0 : T_YH1);
                            st_hi2(th, (uint32_t)row * 128u + (uint32_t)(d & 63) * 2u,
                                   y0, y1);
                        }
                    }
            }
        }
    }
}

extern "C" void kernel_launch(void* const* d_in, const int* in_sizes, int n_in,
                              void* d_out, int out_size) {
    const float* x    = (const float*)d_in[0];
    const float* Wih0 = (const float*)d_in[1];
    const float* Whh0 = (const float*)d_in[2];
    const float* b0   = (const float*)d_in[3];
    const float* Wih1 = (const float*)d_in[4];
    const float* Whh1 = (const float*)d_in[5];
    const float* b1   = (const float*)d_in[6];
    const float* Wfc  = (const float*)d_in[7];
    const float* bfc  = (const float*)d_in[8];
    (void)in_sizes; (void)n_in;

    float* out = (float*)d_out;
    const long long BD = (long long)B_ROWS * DDIM;
    float* ylast  = nullptr;
    float* ystack = nullptr;
    if ((long long)out_size >= BD * (NSTEPS + 1)) {
        ylast  = out;
        ystack = out + BD;
    } else if ((long long)out_size >= BD * NSTEPS) {
        ystack = out;
    } else {
        ylast = out;
    }

    cudaFuncSetAttribute(lstm_hmma_kernel,
                         cudaFuncAttributeMaxDynamicSharedMemorySize, SM_TOTAL);

    prep_kernel<<<64, 256>>>(Wih0, Whh0, Wih1, Whh1, Wfc);
    lstm_hmma_kernel<<<B_ROWS / M_TILE, THREADS, SM_TOTAL>>>(x, b0, b1, bfc, ystack, ylast);
}

// round 16
// speedup vs baseline: 5.7382x; 1.0559x over previous
#include <cuda_runtime.h>
#include <cuda_fp16.h>
#include <cstdint>
#include <cstddef>

#define B_ROWS 32768
#define DDIM   128
#define NSTEPS 32
#define THREADS 256
#define M_TILE 64

// ---------------- packed weight scratch (fp16) ----------------
// [W0h 3x16384][W1h 2x16384][Wfh 8192] half elems.
// Each 16384-elem chunk = [256 n x 64 k], 128B rows, SW128 swizzled.
// Gate chunks use unit-interleaved n: n = (u>>3)*32 + g*8 + (u&7).
__device__ __align__(128) __half g_WB[98304];

#define SWZ128(o) ((o) ^ (((o) >> 3) & 0x70))

static __device__ __forceinline__ uint32_t smem_u32(const void* p) {
    uint32_t a;
    asm("{ .reg .u64 t; cvta.to.shared.u64 t, %1; cvt.u32.u64 %0, t; }" : "=r"(a) : "l"(p));
    return a;
}

// ---------------- mma / ldmatrix / cp.async ----------------
static __device__ __forceinline__ void ldm_x4(uint32_t* r, uint32_t addr) {
    asm volatile("ldmatrix.sync.aligned.m8n8.x4.shared.b16 {%0,%1,%2,%3}, [%4];"
                 : "=r"(r[0]), "=r"(r[1]), "=r"(r[2]), "=r"(r[3]) : "r"(addr));
}
static __device__ __forceinline__ void mma16816(float* c, const uint32_t* a, const uint32_t* b) {
    asm volatile(
        "mma.sync.aligned.m16n8k16.row.col.f32.f16.f16.f32 "
        "{%0,%1,%2,%3}, {%4,%5,%6,%7}, {%8,%9}, {%0,%1,%2,%3};"
        : "+f"(c[0]), "+f"(c[1]), "+f"(c[2]), "+f"(c[3])
        : "r"(a[0]), "r"(a[1]), "r"(a[2]), "r"(a[3]), "r"(b[0]), "r"(b[1]));
}
static __device__ __forceinline__ void cp16(uint32_t dst, const void* src) {
    asm volatile("cp.async.cg.shared.global [%0], [%1], 16;" :: "r"(dst), "l"(src));
}
static __device__ __forceinline__ void cp_commit() {
    asm volatile("cp.async.commit_group;" ::: "memory");
}

// ---------------- fast activation math (MUFU.TANH) ----------------
static __device__ __forceinline__ float tanh_m(float x) {
    float r;
    asm("tanh.approx.f32 %0, %1;" : "=f"(r) : "f"(x));
    return r;
}
static __device__ __forceinline__ float sigm(float x) {
    return fmaf(0.5f, tanh_m(0.5f * x), 0.5f);
}

// ---------------- smem layout (byte offsets in dynamic smem) ----------------
// M=64 rows -> 8KB activation tiles. Lo tile only for H1 (FC 2nd term = Alo*Wh).
#define T_YH0 0
#define T_YH1 8192
#define T_H0H 16384
#define T_H1H 24576
#define T_H1L 32768
#define SM_WBUF 40960               /* 2 x 32KB stream buffers */
#define SM_B0   106496              /* 256 floats */
#define SM_B1   107520              /* 256 floats */
#define SM_BFC  108544              /* 128 floats */
#define SM_TOTAL 109056             /* 2 CTAs/SM */

// ---------------- per-step chunk sequence ----------------
// Recurrent-state chunk FIRST in each phase so epilogue tile overwrites are
// separated from the last reads by >=2 chunk barriers (no epi barrier needed).
// 0: W0h k=h0   A=H0H (old)
// 1: W0h k=y0   A=YH0
// 2: W0h k=y1   A=YH1        -> L0 epilogue (writes H0H, no barrier)
// 3: W1h k=h1   A=H1H (old)
// 4: W1h k=h0   A=H0H (new)  -> L1 epilogue (writes H1H + H1L, no barrier)
// 5: Wf  hi     A=H1H/H1L    -> FC epilogue (2-term, writes YH + gmem)
__constant__ uint32_t c_src[6]   = { 32768, 0, 16384, 65536, 49152, 81920 };
__constant__ uint32_t c_bytes[6] = { 32768, 32768, 32768, 32768, 32768, 16384 };
__constant__ uint32_t c_ahi[6]   = { T_H0H, T_YH0, T_YH1, T_H1H, T_H0H, T_H1H };

// ---------------- weight prep ----------------
__global__ void prep_kernel(const float* __restrict__ Wih0, const float* __restrict__ Whh0,
                            const float* __restrict__ Wih1, const float* __restrict__ Whh1,
                            const float* __restrict__ Wfc) {
    int i = blockIdx.x * blockDim.x + threadIdx.x;
    int stride = gridDim.x * blockDim.x;
    // L0 chunks (fp16 weights), gate-interleaved n. ch0/1 = Wih0 k-blocks, ch2 = Whh0.
    for (int idx = i; idx < 3 * 16384; idx += stride) {
        int ch = idx >> 14, e = idx & 16383, n = e >> 6, kk = e & 63;
        int g = (n >> 3) & 3, u = ((n >> 5) << 3) | (n & 7);
        float w = (ch < 2) ? Wih0[(g * 64 + u) * 128 + ch * 64 + kk]
                           : Whh0[(g * 64 + u) * 64 + kk];
        uint32_t sw = SWZ128((uint32_t)n * 128u + (uint32_t)kk * 2u) >> 1;
        g_WB[ch * 16384 + sw] = __float2half(w);
    }
    // L1 chunks: ch0 = Wih1 (h0 input) at 49152, ch1 = Whh1 (h1 state) at 65536
    for (int idx = i; idx < 2 * 16384; idx += stride) {
        int ch = idx >> 14, e = idx & 16383, n = e >> 6, kk = e & 63;
        int g = (n >> 3) & 3, u = ((n >> 5) << 3) | (n & 7);
        float w = (ch == 0) ? Wih1[(g * 64 + u) * 64 + kk]
                            : Whh1[(g * 64 + u) * 64 + kk];
        uint32_t sw = SWZ128((uint32_t)n * 128u + (uint32_t)kk * 2u) >> 1;
        g_WB[49152 + ch * 16384 + sw] = __float2half(w);
    }
    // FC hi only (16KB) at 81920
    for (int idx = i; idx < 8192; idx += stride) {
        int n = idx >> 6, kk = idx & 63;
        uint32_t sw = SWZ128((uint32_t)n * 128u + (uint32_t)kk * 2u) >> 1;
        g_WB[81920 + sw] = __float2half(Wfc[n * 64 + kk]);
    }
}

// ---------------- activation stores (fp16) ----------------
static __device__ __forceinline__ void st_hi2(char* th, uint32_t off, float a, float b) {
    uint32_t sw = SWZ128(off);
    __half2 hp;
    hp.x = __float2half(a);
    hp.y = __float2half(b);
    *(__half2*)(th + sw) = hp;
}
static __device__ __forceinline__ void st_hilo2(char* th, char* tl, uint32_t off,
                                                float a, float b) {
    uint32_t sw = SWZ128(off);
    __half ah = __float2half(a), bh = __float2half(b);
    __half2 hp; hp.x = ah; hp.y = bh;
    *(__half2*)(th + sw) = hp;
    __half2 lp;
    lp.x = __float2half(a - __half2float(ah));
    lp.y = __float2half(b - __half2float(bh));
    *(__half2*)(tl + sw) = lp;
}

// ---------------- main kernel ----------------
extern __shared__ char smem[];

__global__ __launch_bounds__(THREADS, 2)
void lstm_hmma_kernel(const float* __restrict__ x,
                      const float* __restrict__ b0, const float* __restrict__ b1,
                      const float* __restrict__ bfc,
                      float* __restrict__ ystack, float* __restrict__ ylast) {
    const uint32_t sbase = smem_u32(smem);
    const int tid = threadIdx.x, lane = tid & 31, w = tid >> 5;   // w = n-position (0..7)
    const int row0 = blockIdx.x * M_TILE;

    // ---- init: biases -> smem, x -> Y tiles, zero H tiles ----
    ((float*)(smem + SM_B0))[tid] = b0[tid];
    ((float*)(smem + SM_B1))[tid] = b1[tid];
    if (tid < 128) ((float*)(smem + SM_BFC))[tid] = bfc[tid];
    {
        uint4 z = make_uint4(0, 0, 0, 0);
        for (uint32_t i = (uint32_t)tid * 16u; i < 24576u; i += THREADS * 16u)
            *(uint4*)(smem + T_H0H + i) = z;   // zero H0H, H1H, H1L
        const float4* x4 = (const float4*)(x + (size_t)row0 * 128);
        for (int e = tid; e < M_TILE * 32; e += THREADS) {
            int r = e >> 5, c4 = e & 31;
            float4 v = x4[r * 32 + c4];
            int c = c4 * 4;
            char* th = (char*)smem + ((c < 64) ? T_YH0 : T_YH1);
            uint32_t off = (uint32_t)r * 128u + (uint32_t)(c & 63) * 2u;
            st_hi2(th, off, v.x, v.y);
            st_hi2(th, off + 4, v.z, v.w);
        }
    }

    // ---- per-thread roles ----
    const int l4 = lane >> 2;            // row within 8
    const int ln = lane & 3;             // n-pair selector
    const int u0 = w * 8 + 2 * ln;       // unit pair (gates)
    const uint32_t xm = (uint32_t)(lane & 7) << 4;   // lane-constant swizzle mask
    const int arow = lane & 15;
    const uint32_t hi16 = (uint32_t)((lane >> 4) << 4);
    uint32_t cxk[4];
#pragma unroll
    for (int k = 0; k < 4; ++k) cxk[k] = ((uint32_t)(k * 32) + hi16) ^ xm;

    const float* b0s  = (const float*)(smem + SM_B0);
    const float* b1s  = (const float*)(smem + SM_B1);
    const float* bfcs = (const float*)(smem + SM_BFC);

    float c0s[16], c1s[16];
#pragma unroll
    for (int i = 0; i < 16; ++i) { c0s[i] = 0.0f; c1s[i] = 0.0f; }

    float acc[4][4][4];

    // prologue: issue chunk 0
    {
        const char* src = (const char*)(g_WB + c_src[0]);
        uint32_t dst = sbase + SM_WBUF;
        for (uint32_t off = (uint32_t)tid * 16u; off < 32768u; off += THREADS * 16u)
            cp16(dst + off, src + off);
        cp_commit();
    }

#pragma unroll 1
    for (int t = 0; t < NSTEPS; ++t) {
#pragma unroll 1
        for (int c = 0; c < 6; ++c) {
            const bool isFC = (c == 5);
            const int epi = (c == 2) ? 1 : (c == 4) ? 2 : (c == 5) ? 3 : 0;
            const bool start = (c == 0) | (c == 3) | (c == 5);

            // chunk c arrived (this thread's cp groups drained)
            asm volatile("cp.async.wait_group 0;" ::: "memory");
            // one barrier per chunk: chunk-c writes visible; all warps done with
            // chunk c-1 mma (buffer free); prior epilogue stores visible
            __syncthreads();

            // issue next chunk into the freed buffer
            const bool last = (t == NSTEPS - 1) && (c == 5);
            if (!last) {
                int nc = (c + 1) % 6;
                const char* src = (const char*)(g_WB + c_src[nc]);
                uint32_t dst = sbase + SM_WBUF + (uint32_t)(~c & 1) * 32768u;
                uint32_t nbytes = c_bytes[nc];
                for (uint32_t off = (uint32_t)tid * 16u; off < nbytes; off += THREADS * 16u)
                    cp16(dst + off, src + off);
                cp_commit();
            }

            // ---- acc init at phase start (biases from smem) ----
            if (start) {
                if (isFC) {
                    float bb[2][2];
#pragma unroll
                    for (int v = 0; v < 2; ++v)
#pragma unroll
                        for (int j = 0; j < 2; ++j)
                            bb[v][j] = bfcs[w * 16 + v * 8 + 2 * ln + j];
#pragma unroll
                    for (int s = 0; s < 4; ++s)
#pragma unroll
                        for (int v = 0; v < 2; ++v)
#pragma unroll
                            for (int q = 0; q < 4; ++q)
                                acc[s][v][q] = bb[v][q & 1];
                } else {
                    const float* bs = (c == 0) ? b0s : b1s;
                    float bb[4][2];
#pragma unroll
                    for (int v = 0; v < 4; ++v)
#pragma unroll
                        for (int j = 0; j < 2; ++j)
                            bb[v][j] = bs[v * 64 + u0 + j];
#pragma unroll
                    for (int s = 0; s < 4; ++s)
#pragma unroll
                        for (int v = 0; v < 4; ++v)
#pragma unroll
                            for (int q = 0; q < 4; ++q)
                                acc[s][v][q] = bb[v][q & 1];
                }
            }

            // ---- mma over this chunk (64 k) ----
            const uint32_t buf = sbase + SM_WBUF + (uint32_t)(c & 1) * 32768u;
            const uint32_t ahi = sbase + c_ahi[c];
            const int nb = (isFC ? w * 16 : w * 32) + (lane & 15);
            const uint32_t brow = buf + (uint32_t)nb * 128u;
            const uint32_t abase = ahi + (uint32_t)arow * 128u;

#pragma unroll
            for (int k16 = 0; k16 < 4; ++k16) {
                const uint32_t cx = cxk[k16];
                // B fragments: gates -> 32 n rows (2 ldm); FC -> 16 rows (1 ldm)
                uint32_t bfr[4][2];
                {
                    uint32_t r[4];
                    ldm_x4(r, brow + cx);
                    bfr[0][0] = r[0]; bfr[1][0] = r[1]; bfr[0][1] = r[2]; bfr[1][1] = r[3];
                    if (!isFC) {
                        ldm_x4(r, brow + 2048u + cx);
                        bfr[2][0] = r[0]; bfr[3][0] = r[1]; bfr[2][1] = r[2]; bfr[3][1] = r[3];
                    }
                }
#pragma unroll
                for (int s = 0; s < 4; ++s) {
                    const uint32_t aoff = abase + (uint32_t)(s * 2048) + cx;
                    uint32_t ah[4];
                    ldm_x4(ah, aoff);
                    if (isFC) {
                        uint32_t al[4];
                        ldm_x4(al, aoff + (T_H1L - T_H1H));
#pragma unroll
                        for (int v = 0; v < 2; ++v) {
                            mma16816(acc[s][v], ah, bfr[v]);
                            mma16816(acc[s][v], al, bfr[v]);   // A-residual x W-hi
                        }
                    } else {
#pragma unroll
                        for (int v = 0; v < 4; ++v)
                            mma16816(acc[s][v], ah, bfr[v]);
                    }
                }
            }

            // ---- epilogues (no barriers: chunk reordering makes WAR safe) ----
            if (epi == 1 || epi == 2) {
                float* cst = (epi == 1) ? c0s : c1s;
                char* th = (char*)smem + ((epi == 1) ? T_H0H : T_H1H);
                char* tl = (char*)smem + T_H1L;
#pragma unroll
                for (int s = 0; s < 4; ++s)
#pragma unroll
                    for (int rh = 0; rh < 2; ++rh) {
                        float h2[2];
#pragma unroll
                        for (int j = 0; j < 2; ++j) {
                            float iv = sigm(acc[s][0][rh * 2 + j]);
                            float fv = sigm(acc[s][1][rh * 2 + j]);
                            float gv = tanh_m(acc[s][2][rh * 2 + j]);
                            float ov = sigm(acc[s][3][rh * 2 + j]);
                            int ci = s * 4 + rh * 2 + j;
                            float cv = fmaf(fv, cst[ci], iv * gv);
                            cst[ci] = cv;
                            h2[j] = ov * tanh_m(cv);
                        }
                        int row = s * 16 + l4 + rh * 8;
                        uint32_t off = (uint32_t)row * 128u + (uint32_t)u0 * 2u;
                        if (epi == 1) st_hi2(th, off, h2[0], h2[1]);
                        else          st_hilo2(th, tl, off, h2[0], h2[1]);
                    }
            } else if (epi == 3) {
                // FC epilogue: y = acc (+bias already), write gmem + Y tiles (hi only)
                const size_t tb = (size_t)t * B_ROWS * DDIM;
#pragma unroll
                for (int s = 0; s < 4; ++s)
#pragma unroll
                    for (int rh = 0; rh < 2; ++rh) {
                        int row = s * 16 + l4 + rh * 8;
                        float* ys = ystack ? (ystack + tb + (size_t)(row0 + row) * DDIM)
                                           : nullptr;
                        float* yl = (ylast && t == NSTEPS - 1)
                                        ? (ylast + (size_t)(row0 + row) * DDIM) : nullptr;
#pragma unroll
                        for (int v = 0; v < 2; ++v) {
                            int d = w * 16 + v * 8 + 2 * ln;
                            float y0 = acc[s][v][rh * 2 + 0];
                            float y1 = acc[s][v][rh * 2 + 1];
                            if (ys) { float2 p = make_float2(y0, y1); *(float2*)(ys + d) = p; }
                            if (yl) { float2 p = make_float2(y0, y1); *(float2*)(yl + d) = p; }
                            char* th = (char*)smem + ((d < 64) ? T_YH0 : T_YH1);
                            st_hi2(th, (uint32_t)row * 128u + (uint32_t)(d & 63) * 2u,
                                   y0, y1);
                        }
                    }
            }
        }
    }
}

extern "C" void kernel_launch(void* const* d_in, const int* in_sizes, int n_in,
                              void* d_out, int out_size) {
    const float* x    = (const float*)d_in[0];
    const float* Wih0 = (const float*)d_in[1];
    const float* Whh0 = (const float*)d_in[2];
    const float* b0   = (const float*)d_in[3];
    const float* Wih1 = (const float*)d_in[4];
    const float* Whh1 = (const float*)d_in[5];
    const float* b1   = (const float*)d_in[6];
    const float* Wfc  = (const float*)d_in[7];
    const float* bfc  = (const float*)d_in[8];
    (void)in_sizes; (void)n_in;

    float* out = (float*)d_out;
    const long long BD = (long long)B_ROWS * DDIM;
    float* ylast  = nullptr;
    float* ystack = nullptr;
    if ((long long)out_size >= BD * (NSTEPS + 1)) {
        ylast  = out;
        ystack = out + BD;
    } else if ((long long)out_size >= BD * NSTEPS) {
        ystack = out;
    } else {
        ylast = out;
    }

    cudaFuncSetAttribute(lstm_hmma_kernel,
                         cudaFuncAttributeMaxDynamicSharedMemorySize, SM_TOTAL);

    prep_kernel<<<64, 256>>>(Wih0, Whh0, Wih1, Whh1, Wfc);
    lstm_hmma_kernel<<<B_ROWS / M_TILE, THREADS, SM_TOTAL>>>(x, b0, b1, bfc, ystack, ylast);
}

// round 17
// speedup vs baseline: 6.2860x; 1.0955x over previous
#include <cuda_runtime.h>
#include <cuda_fp16.h>
#include <cstdint>
#include <cstddef>

#define B_ROWS 32768
#define DDIM   128
#define NSTEPS 32
#define THREADS 256
#define M_TILE 64

// ---------------- packed weight scratch (fp16) ----------------
// [W0h 3x16384][W1h 2x16384][Wfh 8192] half elems.
// Each 16384-elem chunk = [256 n x 64 k], 128B rows, SW128 swizzled.
// Gate chunks use unit-interleaved n: n = (u>>3)*32 + g*8 + (u&7).
__device__ __align__(128) __half g_WB[98304];

#define SWZ128(o) ((o) ^ (((o) >> 3) & 0x70))

static __device__ __forceinline__ uint32_t smem_u32(const void* p) {
    uint32_t a;
    asm("{ .reg .u64 t; cvta.to.shared.u64 t, %1; cvt.u32.u64 %0, t; }" : "=r"(a) : "l"(p));
    return a;
}

// ---------------- mma / ldmatrix ----------------
static __device__ __forceinline__ void ldm_x4(uint32_t* r, uint32_t addr) {
    asm volatile("ldmatrix.sync.aligned.m8n8.x4.shared.b16 {%0,%1,%2,%3}, [%4];"
                 : "=r"(r[0]), "=r"(r[1]), "=r"(r[2]), "=r"(r[3]) : "r"(addr));
}
static __device__ __forceinline__ void mma16816(float* c, const uint32_t* a, const uint32_t* b) {
    asm volatile(
        "mma.sync.aligned.m16n8k16.row.col.f32.f16.f16.f32 "
        "{%0,%1,%2,%3}, {%4,%5,%6,%7}, {%8,%9}, {%0,%1,%2,%3};"
        : "+f"(c[0]), "+f"(c[1]), "+f"(c[2]), "+f"(c[3])
        : "r"(a[0]), "r"(a[1]), "r"(a[2]), "r"(a[3]), "r"(b[0]), "r"(b[1]));
}

// ---------------- bulk async copy + mbarrier ----------------
static __device__ __forceinline__ void bulk_g2s(uint32_t dst, const void* src,
                                                uint32_t bytes, uint32_t mbar) {
    asm volatile(
        "cp.async.bulk.shared::cta.global.mbarrier::complete_tx::bytes [%0], [%1], %2, [%3];"
        :: "r"(dst), "l"(src), "r"(bytes), "r"(mbar) : "memory");
}
#define MBAR_INIT(mb, c) \
    asm volatile("mbarrier.init.shared.b64 [%0], %1;" :: "r"(mb), "r"((uint32_t)(c)) : "memory")
#define MBAR_EXPECT_TX(mb, bytes) \
    asm volatile("mbarrier.arrive.expect_tx.shared.b64 _, [%0], %1;" \
                 :: "r"(mb), "r"((uint32_t)(bytes)) : "memory")
static __device__ __forceinline__ void mbar_wait(uint32_t mbar, uint32_t parity) {
    asm volatile(
        "{\n\t.reg .pred P1;\n\t"
        "WL_%=:\n\t"
        "mbarrier.try_wait.parity.acquire.cta.shared::cta.b64 P1, [%0], %1, 0x989680;\n\t"
        "@P1 bra.uni WD_%=;\n\t"
        "bra.uni WL_%=;\n\t"
        "WD_%=:\n\t}"
        :: "r"(mbar), "r"(parity) : "memory");
}

// ---------------- fast activation math (MUFU.TANH) ----------------
static __device__ __forceinline__ float tanh_m(float x) {
    float r;
    asm("tanh.approx.f32 %0, %1;" : "=f"(r) : "f"(x));
    return r;
}
static __device__ __forceinline__ float sigm(float x) {
    return fmaf(0.5f, tanh_m(0.5f * x), 0.5f);
}

// ---------------- smem layout (byte offsets in dynamic smem) ----------------
// M=64 rows -> 8KB activation tiles. Lo tile only for H1 (FC 2nd term = Alo*Wh).
#define T_YH0 0
#define T_YH1 8192
#define T_H0H 16384
#define T_H1H 24576
#define T_H1L 32768
#define SM_WBUF 40960               /* 2 x 32KB stream buffers */
#define SM_B0   106496              /* 256 floats */
#define SM_B1   107520              /* 256 floats */
#define SM_BFC  108544              /* 128 floats */
#define SM_MBAR 109056              /* 2 mbarriers (8B each) */
#define SM_TOTAL 109120             /* 2 CTAs/SM */

// ---------------- per-step chunk sequence ----------------
// Recurrent-state chunk FIRST in each phase so epilogue tile overwrites are
// separated from the last reads by >=2 chunk barriers (no epi barrier needed).
// 0: W0h k=h0   A=H0H (old)
// 1: W0h k=y0   A=YH0
// 2: W0h k=y1   A=YH1        -> L0 epilogue (writes H0H, no barrier)
// 3: W1h k=h1   A=H1H (old)
// 4: W1h k=h0   A=H0H (new)  -> L1 epilogue (writes H1H + H1L, no barrier)
// 5: Wf  hi     A=H1H/H1L    -> FC epilogue (2-term, writes YH + gmem)
__constant__ uint32_t c_src[6]   = { 32768, 0, 16384, 65536, 49152, 81920 };
__constant__ uint32_t c_bytes[6] = { 32768, 32768, 32768, 32768, 32768, 16384 };
__constant__ uint32_t c_ahi[6]   = { T_H0H, T_YH0, T_YH1, T_H1H, T_H0H, T_H1H };

// ---------------- weight prep ----------------
__global__ void prep_kernel(const float* __restrict__ Wih0, const float* __restrict__ Whh0,
                            const float* __restrict__ Wih1, const float* __restrict__ Whh1,
                            const float* __restrict__ Wfc) {
    int i = blockIdx.x * blockDim.x + threadIdx.x;
    int stride = gridDim.x * blockDim.x;
    // L0 chunks (fp16 weights), gate-interleaved n. ch0/1 = Wih0 k-blocks, ch2 = Whh0.
    for (int idx = i; idx < 3 * 16384; idx += stride) {
        int ch = idx >> 14, e = idx & 16383, n = e >> 6, kk = e & 63;
        int g = (n >> 3) & 3, u = ((n >> 5) << 3) | (n & 7);
        float w = (ch < 2) ? Wih0[(g * 64 + u) * 128 + ch * 64 + kk]
                           : Whh0[(g * 64 + u) * 64 + kk];
        uint32_t sw = SWZ128((uint32_t)n * 128u + (uint32_t)kk * 2u) >> 1;
        g_WB[ch * 16384 + sw] = __float2half(w);
    }
    // L1 chunks: ch0 = Wih1 (h0 input) at 49152, ch1 = Whh1 (h1 state) at 65536
    for (int idx = i; idx < 2 * 16384; idx += stride) {
        int ch = idx >> 14, e = idx & 16383, n = e >> 6, kk = e & 63;
        int g = (n >> 3) & 3, u = ((n >> 5) << 3) | (n & 7);
        float w = (ch == 0) ? Wih1[(g * 64 + u) * 64 + kk]
                            : Whh1[(g * 64 + u) * 64 + kk];
        uint32_t sw = SWZ128((uint32_t)n * 128u + (uint32_t)kk * 2u) >> 1;
        g_WB[49152 + ch * 16384 + sw] = __float2half(w);
    }
    // FC hi only (16KB) at 81920
    for (int idx = i; idx < 8192; idx += stride) {
        int n = idx >> 6, kk = idx & 63;
        uint32_t sw = SWZ128((uint32_t)n * 128u + (uint32_t)kk * 2u) >> 1;
        g_WB[81920 + sw] = __float2half(Wfc[n * 64 + kk]);
    }
}

// ---------------- activation stores (fp16) ----------------
static __device__ __forceinline__ void st_hi2(char* th, uint32_t off, float a, float b) {
    uint32_t sw = SWZ128(off);
    __half2 hp;
    hp.x = __float2half(a);
    hp.y = __float2half(b);
    *(__half2*)(th + sw) = hp;
}
static __device__ __forceinline__ void st_hilo2(char* th, char* tl, uint32_t off,
                                                float a, float b) {
    uint32_t sw = SWZ128(off);
    __half ah = __float2half(a), bh = __float2half(b);
    __half2 hp; hp.x = ah; hp.y = bh;
    *(__half2*)(th + sw) = hp;
    __half2 lp;
    lp.x = __float2half(a - __half2float(ah));
    lp.y = __float2half(b - __half2float(bh));
    *(__half2*)(tl + sw) = lp;
}

// ---------------- main kernel ----------------
extern __shared__ char smem[];

__global__ __launch_bounds__(THREADS, 2)
void lstm_hmma_kernel(const float* __restrict__ x,
                      const float* __restrict__ b0, const float* __restrict__ b1,
                      const float* __restrict__ bfc,
                      float* __restrict__ ystack, float* __restrict__ ylast) {
    const uint32_t sbase = smem_u32(smem);
    const int tid = threadIdx.x, lane = tid & 31, w = tid >> 5;   // w = n-position (0..7)
    const int row0 = blockIdx.x * M_TILE;

    // ---- init: biases -> smem, x -> Y tiles, zero H tiles, mbars ----
    ((float*)(smem + SM_B0))[tid] = b0[tid];
    ((float*)(smem + SM_B1))[tid] = b1[tid];
    if (tid < 128) ((float*)(smem + SM_BFC))[tid] = bfc[tid];
    {
        uint4 z = make_uint4(0, 0, 0, 0);
        for (uint32_t i = (uint32_t)tid * 16u; i < 24576u; i += THREADS * 16u)
            *(uint4*)(smem + T_H0H + i) = z;   // zero H0H, H1H, H1L
        const float4* x4 = (const float4*)(x + (size_t)row0 * 128);
        for (int e = tid; e < M_TILE * 32; e += THREADS) {
            int r = e >> 5, c4 = e & 31;
            float4 v = x4[r * 32 + c4];
            int c = c4 * 4;
            char* th = (char*)smem + ((c < 64) ? T_YH0 : T_YH1);
            uint32_t off = (uint32_t)r * 128u + (uint32_t)(c & 63) * 2u;
            st_hi2(th, off, v.x, v.y);
            st_hi2(th, off + 4, v.z, v.w);
        }
    }
    if (tid == 0) {
        MBAR_INIT(sbase + SM_MBAR, 1);
        MBAR_INIT(sbase + SM_MBAR + 8, 1);
    }
    __syncthreads();   // mbars + tiles initialized before first wait / first bulk

    // prologue: issue chunk 0 (single thread, bulk copy)
    if (tid == 0) {
        MBAR_EXPECT_TX(sbase + SM_MBAR, 32768u);
        bulk_g2s(sbase + SM_WBUF, (const char*)(g_WB + c_src[0]), 32768u, sbase + SM_MBAR);
    }

    // ---- per-thread roles ----
    const int l4 = lane >> 2;            // row within 8
    const int ln = lane & 3;             // n-pair selector
    const int u0 = w * 8 + 2 * ln;       // unit pair (gates)
    const uint32_t xm = (uint32_t)(lane & 7) << 4;   // lane-constant swizzle mask
    const int arow = lane & 15;
    const uint32_t hi16 = (uint32_t)((lane >> 4) << 4);
    uint32_t cxk[4];
#pragma unroll
    for (int k = 0; k < 4; ++k) cxk[k] = ((uint32_t)(k * 32) + hi16) ^ xm;

    const float* b0s  = (const float*)(smem + SM_B0);
    const float* b1s  = (const float*)(smem + SM_B1);
    const float* bfcs = (const float*)(smem + SM_BFC);

    float c0s[16], c1s[16];
#pragma unroll
    for (int i = 0; i < 16; ++i) { c0s[i] = 0.0f; c1s[i] = 0.0f; }

    float acc[4][4][4];

#pragma unroll 1
    for (int t = 0; t < NSTEPS; ++t) {
#pragma unroll 1
        for (int c = 0; c < 6; ++c) {
            const bool isFC = (c == 5);
            const int epi = (c == 2) ? 1 : (c == 4) ? 2 : (c == 5) ? 3 : 0;
            const bool start = (c == 0) | (c == 3) | (c == 5);
            const int gc = t * 6 + c;    // gc parity == c parity (6 chunks/step)

            // wait for chunk c data (bulk complete_tx on mbar[c&1])
            mbar_wait(sbase + SM_MBAR + (uint32_t)(c & 1) * 8u, (uint32_t)((gc >> 1) & 1));
            // one barrier per chunk: all warps done with chunk c-1 mma (other
            // buffer free for the next bulk); prior epilogue stores visible
            __syncthreads();

            // issue next chunk into the freed buffer (single thread)
            const bool last = (t == NSTEPS - 1) && (c == 5);
            if (!last && tid == 0) {
                int nc = (c + 1) % 6;
                uint32_t mb = sbase + SM_MBAR + (uint32_t)(~c & 1) * 8u;
                uint32_t nbytes = c_bytes[nc];
                MBAR_EXPECT_TX(mb, nbytes);
                bulk_g2s(sbase + SM_WBUF + (uint32_t)(~c & 1) * 32768u,
                         (const char*)(g_WB + c_src[nc]), nbytes, mb);
            }

            // ---- acc init at phase start (biases from smem) ----
            if (start) {
                if (isFC) {
                    float bb[2][2];
#pragma unroll
                    for (int v = 0; v < 2; ++v)
#pragma unroll
                        for (int j = 0; j < 2; ++j)
                            bb[v][j] = bfcs[w * 16 + v * 8 + 2 * ln + j];
#pragma unroll
                    for (int s = 0; s < 4; ++s)
#pragma unroll
                        for (int v = 0; v < 2; ++v)
#pragma unroll
                            for (int q = 0; q < 4; ++q)
                                acc[s][v][q] = bb[v][q & 1];
                } else {
                    const float* bs = (c == 0) ? b0s : b1s;
                    float bb[4][2];
#pragma unroll
                    for (int v = 0; v < 4; ++v)
#pragma unroll
                        for (int j = 0; j < 2; ++j)
                            bb[v][j] = bs[v * 64 + u0 + j];
#pragma unroll
                    for (int s = 0; s < 4; ++s)
#pragma unroll
                        for (int v = 0; v < 4; ++v)
#pragma unroll
                            for (int q = 0; q < 4; ++q)
                                acc[s][v][q] = bb[v][q & 1];
                }
            }

            // ---- mma over this chunk (64 k) ----
            const uint32_t buf = sbase + SM_WBUF + (uint32_t)(c & 1) * 32768u;
            const uint32_t ahi = sbase + c_ahi[c];
            const int nb = (isFC ? w * 16 : w * 32) + (lane & 15);
            const uint32_t brow = buf + (uint32_t)nb * 128u;
            const uint32_t abase = ahi + (uint32_t)arow * 128u;

#pragma unroll
            for (int k16 = 0; k16 < 4; ++k16) {
                const uint32_t cx = cxk[k16];
                // B fragments: gates -> 32 n rows (2 ldm); FC -> 16 rows (1 ldm)
                uint32_t bfr[4][2];
                {
                    uint32_t r[4];
                    ldm_x4(r, brow + cx);
                    bfr[0][0] = r[0]; bfr[1][0] = r[1]; bfr[0][1] = r[2]; bfr[1][1] = r[3];
                    if (!isFC) {
                        ldm_x4(r, brow + 2048u + cx);
                        bfr[2][0] = r[0]; bfr[3][0] = r[1]; bfr[2][1] = r[2]; bfr[3][1] = r[3];
                    }
                }
#pragma unroll
                for (int s = 0; s < 4; ++s) {
                    const uint32_t aoff = abase + (uint32_t)(s * 2048) + cx;
                    uint32_t ah[4];
                    ldm_x4(ah, aoff);
                    if (isFC) {
                        uint32_t al[4];
                        ldm_x4(al, aoff + (T_H1L - T_H1H));
#pragma unroll
                        for (int v = 0; v < 2; ++v) {
                            mma16816(acc[s][v], ah, bfr[v]);
                            mma16816(acc[s][v], al, bfr[v]);   // A-residual x W-hi
                        }
                    } else {
#pragma unroll
                        for (int v = 0; v < 4; ++v)
                            mma16816(acc[s][v], ah, bfr[v]);
                    }
                }
            }

            // ---- epilogues (no barriers: chunk reordering makes WAR safe) ----
            if (epi == 1 || epi == 2) {
                float* cst = (epi == 1) ? c0s : c1s;
                char* th = (char*)smem + ((epi == 1) ? T_H0H : T_H1H);
                char* tl = (char*)smem + T_H1L;
#pragma unroll
                for (int s = 0; s < 4; ++s)
#pragma unroll
                    for (int rh = 0; rh < 2; ++rh) {
                        float h2[2];
#pragma unroll
                        for (int j = 0; j < 2; ++j) {
                            float iv = sigm(acc[s][0][rh * 2 + j]);
                            float fv = sigm(acc[s][1][rh * 2 + j]);
                            float gv = tanh_m(acc[s][2][rh * 2 + j]);
                            float ov = sigm(acc[s][3][rh * 2 + j]);
                            int ci = s * 4 + rh * 2 + j;
                            float cv = fmaf(fv, cst[ci], iv * gv);
                            cst[ci] = cv;
                            h2[j] = ov * tanh_m(cv);
                        }
                        int row = s * 16 + l4 + rh * 8;
                        uint32_t off = (uint32_t)row * 128u + (uint32_t)u0 * 2u;
                        if (epi == 1) st_hi2(th, off, h2[0], h2[1]);
                        else          st_hilo2(th, tl, off, h2[0], h2[1]);
                    }
            } else if (epi == 3) {
                // FC epilogue: y = acc (+bias already), write gmem + Y tiles (hi only)
                const size_t tb = (size_t)t * B_ROWS * DDIM;
#pragma unroll
                for (int s = 0; s < 4; ++s)
#pragma unroll
                    for (int rh = 0; rh < 2; ++rh) {
                        int row = s * 16 + l4 + rh * 8;
                        float* ys = ystack ? (ystack + tb + (size_t)(row0 + row) * DDIM)
                                           : nullptr;
                        float* yl = (ylast && t == NSTEPS - 1)
                                        ? (ylast + (size_t)(row0 + row) * DDIM) : nullptr;
#pragma unroll
                        for (int v = 0; v < 2; ++v) {
                            int d = w * 16 + v * 8 + 2 * ln;
                            float y0 = acc[s][v][rh * 2 + 0];
                            float y1 = acc[s][v][rh * 2 + 1];
                            if (ys) { float2 p = make_float2(y0, y1); *(float2*)(ys + d) = p; }
                            if (yl) { float2 p = make_float2(y0, y1); *(float2*)(yl + d) = p; }
                            char* th = (char*)smem + ((d < 64) ? T_YH0 : T_YH1);
                            st_hi2(th, (uint32_t)row * 128u + (uint32_t)(d & 63) * 2u,
                                   y0, y1);
                        }
                    }
            }
        }
    }
}

extern "C" void kernel_launch(void* const* d_in, const int* in_sizes, int n_in,
                              void* d_out, int out_size) {
    const float* x    = (const float*)d_in[0];
    const float* Wih0 = (const float*)d_in[1];
    const float* Whh0 = (const float*)d_in[2];
    const float* b0   = (const float*)d_in[3];
    const float* Wih1 = (const float*)d_in[4];
    const float* Whh1 = (const float*)d_in[5];
    const float* b1   = (const float*)d_in[6];
    const float* Wfc  = (const float*)d_in[7];
    const float* bfc  = (const float*)d_in[8];
    (void)in_sizes; (void)n_in;

    float* out = (float*)d_out;
    const long long BD = (long long)B_ROWS * DDIM;
    float* ylast  = nullptr;
    float* ystack = nullptr;
    if ((long long)out_size >= BD * (NSTEPS + 1)) {
        ylast  = out;
        ystack = out + BD;
    } else if ((long long)out_size >= BD * NSTEPS) {
        ystack = out;
    } else {
        ylast = out;
    }

    cudaFuncSetAttribute(lstm_hmma_kernel,
                         cudaFuncAttributeMaxDynamicSharedMemorySize, SM_TOTAL);

    prep_kernel<<<64, 256>>>(Wih0, Whh0, Wih1, Whh1, Wfc);
    lstm_hmma_kernel<<<B_ROWS / M_TILE, THREADS, SM_TOTAL>>>(x, b0, b1, bfc, ystack, ylast);
}